// round 1
// baseline (speedup 1.0000x reference)
#include <cuda_runtime.h>
#include <math.h>

#define BATCH 2048
#define NZ 128
#define NGEN 8
#define TS 16
#define NTILES 136   // ceil((2048 + 8*15)/16)

// ---------------- device scratch (no allocations allowed) ----------------
__device__ float d_h1[BATCH * 256];     // FC1 output
__device__ float d_h2[BATCH * 1568];    // FC2 output (conv input)
__device__ int   d_perm[NTILES * TS];   // samples grouped by generator, -1 padded
__device__ int   d_tileg[NTILES];       // generator per tile, -1 = empty

__device__ __forceinline__ float lrelu(float x) { return x > 0.f ? x : 0.2f * x; }

// ---------------- K0: group samples by generator into padded 16-tiles ----
__global__ void group_kernel(const int* __restrict__ g_idx) {
    __shared__ int cnt[NGEN], base[NGEN], cur[NGEN];
    int tid = threadIdx.x;
    if (tid < NGEN) { cnt[tid] = 0; cur[tid] = 0; }
    __syncthreads();
    for (int b = tid; b < BATCH; b += blockDim.x)
        atomicAdd(&cnt[g_idx[b]], 1);
    for (int i = tid; i < NTILES * TS; i += blockDim.x)
        d_perm[i] = -1;
    __syncthreads();
    if (tid == 0) {
        int off = 0;
        for (int g = 0; g < NGEN; g++) {
            base[g] = off;
            off += ((cnt[g] + TS - 1) / TS) * TS;
        }
    }
    __syncthreads();
    for (int b = tid; b < BATCH; b += blockDim.x) {
        int g = g_idx[b];
        int p = atomicAdd(&cur[g], 1);
        d_perm[base[g] + p] = b;
    }
    for (int t = tid; t < NTILES; t += blockDim.x) {
        int start = t * TS, gg = -1;
        for (int g = 0; g < NGEN; g++) {
            int padded = ((cnt[g] + TS - 1) / TS) * TS;
            if (start >= base[g] && start < base[g] + padded) gg = g;
        }
        d_tileg[t] = gg;
    }
}

// ---------------- K1: FC1  h1 = lrelu(z @ W1[g] + b1[g]) ------------------
__global__ void __launch_bounds__(256) fc1_kernel(
    const float* __restrict__ z, const float* __restrict__ W1,
    const float* __restrict__ b1)
{
    int t = blockIdx.x;
    int g = d_tileg[t];
    if (g < 0) return;
    __shared__ int sids[TS];
    __shared__ float zsm[TS * 130];
    __shared__ __align__(16) float wst[16 * 256];
    int tid = threadIdx.x;
    if (tid < TS) sids[tid] = d_perm[t * TS + tid];
    __syncthreads();
    for (int i = tid; i < TS * NZ; i += 256) {
        int s = i >> 7, k = i & 127;
        int b = sids[s];
        zsm[s * 130 + k] = (b >= 0) ? z[b * NZ + k] : 0.f;
    }
    int s = tid >> 4, c = tid & 15;
    float acc[16];
#pragma unroll
    for (int j = 0; j < 16; j++) acc[j] = 0.f;
    const float* Wg = W1 + (size_t)g * NZ * 256;
    for (int kc = 0; kc < 8; kc++) {
        __syncthreads();
#pragma unroll
        for (int j = 0; j < 16; j++) {
            int idx = tid + 256 * j;
            wst[idx] = Wg[(kc * 16 + (idx >> 8)) * 256 + (idx & 255)];
        }
        __syncthreads();
#pragma unroll
        for (int k = 0; k < 16; k++) {
            float zv = zsm[s * 130 + kc * 16 + k];
            const float4* wp = (const float4*)&wst[k * 256 + c * 16];
#pragma unroll
            for (int j = 0; j < 4; j++) {
                float4 w = wp[j];
                acc[4 * j + 0] += zv * w.x;
                acc[4 * j + 1] += zv * w.y;
                acc[4 * j + 2] += zv * w.z;
                acc[4 * j + 3] += zv * w.w;
            }
        }
    }
    int b = sids[s];
    if (b >= 0) {
#pragma unroll
        for (int j = 0; j < 16; j++)
            acc[j] = lrelu(acc[j] + b1[g * 256 + c * 16 + j]);
        float4* dst = (float4*)&d_h1[b * 256 + c * 16];
#pragma unroll
        for (int j = 0; j < 4; j++)
            dst[j] = make_float4(acc[4 * j], acc[4 * j + 1], acc[4 * j + 2], acc[4 * j + 3]);
    }
}

// ---------------- K2: FC2  h2 = lrelu(h1 @ W2[g] + b2[g]) -----------------
// grid (tile, q): q selects 224 of the 1568 outputs. Thread owns 14
// consecutive outputs for one sample -> float2 smem weight loads.
__global__ void __launch_bounds__(256) fc2_kernel(
    const float* __restrict__ W2, const float* __restrict__ b2)
{
    int t = blockIdx.x, q = blockIdx.y;
    int g = d_tileg[t];
    if (g < 0) return;
    __shared__ int sids[TS];
    __shared__ float h1sm[TS * 257];
    __shared__ __align__(8) float wst[16 * 224];
    int tid = threadIdx.x;
    if (tid < TS) sids[tid] = d_perm[t * TS + tid];
    __syncthreads();
    for (int i = tid; i < TS * 256; i += 256) {
        int s = i >> 8, k = i & 255;
        int b = sids[s];
        h1sm[s * 257 + k] = (b >= 0) ? d_h1[b * 256 + k] : 0.f;
    }
    int s = tid >> 4, c = tid & 15;
    float acc[14];
#pragma unroll
    for (int j = 0; j < 14; j++) acc[j] = 0.f;
    const float* Wg = W2 + (size_t)g * 256 * 1568 + q * 224;
    for (int kc = 0; kc < 16; kc++) {
        __syncthreads();
#pragma unroll
        for (int j = 0; j < 14; j++) {
            int idx = tid + 256 * j;
            int row = idx / 224, col = idx - row * 224;
            wst[idx] = Wg[(kc * 16 + row) * 1568 + col];
        }
        __syncthreads();
#pragma unroll
        for (int k = 0; k < 16; k++) {
            float hv = h1sm[s * 257 + kc * 16 + k];
            const float2* wp = (const float2*)&wst[k * 224 + c * 14];
#pragma unroll
            for (int j = 0; j < 7; j++) {
                float2 w = wp[j];
                acc[2 * j + 0] += hv * w.x;
                acc[2 * j + 1] += hv * w.y;
            }
        }
    }
    int b = sids[s];
    if (b >= 0) {
#pragma unroll
        for (int j = 0; j < 14; j++) {
            int o = q * 224 + c * 14 + j;
            d_h2[(size_t)b * 1568 + o] = lrelu(acc[j] + b2[g * 1568 + o]);
        }
    }
}

// ---------------- K3: conv chain, one CTA per sample ----------------------
// ConvT stride2 k4 p1 decomposed into 4 parity classes, each a 2x2-tap conv:
//   jy = (1-py) + 2d, padded input row = my + 1 + py - d   (d in {0,1})
// Inputs are zero-padded in smem so no boundary branches.
#define SM_X1 0       // 32 x 9 x 9   = 2592
#define SM_X2 2592    // 16 x 16 x 16 = 4096
#define SM_X3 6688    // 8 x 30 x 30  = 7200
#define SM_W  13888   // 8192 weight buffer (cw1; later cw2 + cw3@+2048)
#define SM_TOTALF 22080

__global__ void __launch_bounds__(256) conv_kernel(
    const int* __restrict__ g_idx,
    const float* __restrict__ cw1, const float* __restrict__ cb1,
    const float* __restrict__ cw2, const float* __restrict__ cb2,
    const float* __restrict__ cw3, const float* __restrict__ cb3,
    float* __restrict__ out)
{
    extern __shared__ float sm[];
    int b = blockIdx.x;
    int g = g_idx[b];
    int tid = threadIdx.x;
    float* x1 = sm + SM_X1;
    float* x2 = sm + SM_X2;
    float* x3 = sm + SM_X3;
    float* wb = sm + SM_W;

    // zero all padded activation buffers
    for (int i = tid; i < SM_W; i += 256) sm[i] = 0.f;
    // cw1 [32][16][4][4] -> [ci][jy][jx][co16]
    for (int i = tid; i < 8192; i += 256) {
        int ci = i >> 8, co = (i >> 4) & 15, jy = (i >> 2) & 3, jx = i & 3;
        wb[((ci * 4 + jy) * 4 + jx) * 16 + co] = cw1[g * 8192 + i];
    }
    __syncthreads();
    // load conv input [32,7,7] into padded interior
    for (int i = tid; i < 1568; i += 256) {
        int ci = i / 49, r = (i / 7) % 7, cc = i % 7;
        x1[(ci * 9 + r + 1) * 9 + cc + 1] = d_h2[(size_t)b * 1568 + i];
    }
    __syncthreads();

    // ---- convT1: [32,7,7] -> [16,14,14] ----
    if (tid < 224) {
        int cls = tid / 56;
        int py = cls >> 1, px = cls & 1;
        int v = tid - cls * 56;
        int cob = v / 7, my = v - cob * 7;
        int co = cob * 2;
        float a0[7], a1[7];
#pragma unroll
        for (int m = 0; m < 7; m++) { a0[m] = 0.f; a1[m] = 0.f; }
        for (int ci = 0; ci < 32; ci++) {
#pragma unroll
            for (int d = 0; d < 2; d++) {
                int jy = (1 - py) + 2 * d;
                const float* xr = &x1[(ci * 9 + my + 1 + py - d) * 9];
#pragma unroll
                for (int e = 0; e < 2; e++) {
                    int jx = (1 - px) + 2 * e;
                    const float* wp = &wb[((ci * 4 + jy) * 4 + jx) * 16 + co];
                    float w0 = wp[0], w1 = wp[1];
                    const float* xp = xr + 1 + px - e;
#pragma unroll
                    for (int m = 0; m < 7; m++) {
                        float xv = xp[m];
                        a0[m] += w0 * xv;
                        a1[m] += w1 * xv;
                    }
                }
            }
        }
        float bb0 = cb1[g * 16 + co], bb1 = cb1[g * 16 + co + 1];
        int oy = 2 * my + py;
#pragma unroll
        for (int m = 0; m < 7; m++) {
            int ox = 2 * m + px;
            x2[(co * 16 + oy + 1) * 16 + ox + 1] = lrelu(a0[m] + bb0);
            x2[((co + 1) * 16 + oy + 1) * 16 + ox + 1] = lrelu(a1[m] + bb1);
        }
    }
    __syncthreads();
    // cw2 [16][8][4][4] -> [ci][jy][jx][co8]; cw3 -> wb+2048
    for (int i = tid; i < 2048; i += 256) {
        int ci = i >> 7, co = (i >> 4) & 7, jy = (i >> 2) & 3, jx = i & 3;
        wb[((ci * 4 + jy) * 4 + jx) * 8 + co] = cw2[g * 2048 + i];
    }
    if (tid < 72) wb[2048 + tid] = cw3[g * 72 + tid];
    __syncthreads();

    // ---- convT2: [16,14,14] -> [8,28,28] ----
    if (tid < 224) {
        int cls = tid / 56;
        int py = cls >> 1, px = cls & 1;
        int v = tid - cls * 56;
        int cob = v / 14, my = v - cob * 14;
        int co = cob * 2;
        float a0[14], a1[14];
#pragma unroll
        for (int m = 0; m < 14; m++) { a0[m] = 0.f; a1[m] = 0.f; }
        for (int ci = 0; ci < 16; ci++) {
#pragma unroll
            for (int d = 0; d < 2; d++) {
                int jy = (1 - py) + 2 * d;
                const float* xr = &x2[(ci * 16 + my + 1 + py - d) * 16];
#pragma unroll
                for (int e = 0; e < 2; e++) {
                    int jx = (1 - px) + 2 * e;
                    const float* wp = &wb[((ci * 4 + jy) * 4 + jx) * 8 + co];
                    float w0 = wp[0], w1 = wp[1];
                    const float* xp = xr + 1 + px - e;
#pragma unroll
                    for (int m = 0; m < 14; m++) {
                        float xv = xp[m];
                        a0[m] += w0 * xv;
                        a1[m] += w1 * xv;
                    }
                }
            }
        }
        float bb0 = cb2[g * 8 + co], bb1 = cb2[g * 8 + co + 1];
        int oy = 2 * my + py;
#pragma unroll
        for (int m = 0; m < 14; m++) {
            int ox = 2 * m + px;
            x3[(co * 30 + oy + 1) * 30 + ox + 1] = lrelu(a0[m] + bb0);
            x3[((co + 1) * 30 + oy + 1) * 30 + ox + 1] = lrelu(a1[m] + bb1);
        }
    }
    __syncthreads();

    // ---- convT3 (stride1 k3 p1): [8,28,28] -> [1,28,28], tanh ----
    float bb = cb3[g];
    for (int p = tid; p < 784; p += 256) {
        int oy = p / 28, ox = p - oy * 28;
        float acc = bb;
#pragma unroll
        for (int ci = 0; ci < 8; ci++) {
#pragma unroll
            for (int jy = 0; jy < 3; jy++) {
                const float* xr = &x3[(ci * 30 + oy + 2 - jy) * 30 + ox];
                const float* wr = &wb[2048 + ci * 9 + jy * 3];
                acc += xr[2] * wr[0] + xr[1] * wr[1] + xr[0] * wr[2];
            }
        }
        out[(size_t)b * 784 + p] = tanhf(acc);
    }
}

// ---------------- launch ----------------
extern "C" void kernel_launch(void* const* d_in, const int* in_sizes, int n_in,
                              void* d_out, int out_size)
{
    (void)in_sizes; (void)n_in; (void)out_size;
    const float* z   = (const float*)d_in[0];
    const int*   gi  = (const int*)d_in[1];
    const float* W1  = (const float*)d_in[2];
    const float* b1  = (const float*)d_in[3];
    const float* W2  = (const float*)d_in[4];
    const float* b2  = (const float*)d_in[5];
    const float* cw1 = (const float*)d_in[6];
    const float* cb1 = (const float*)d_in[7];
    const float* cw2 = (const float*)d_in[8];
    const float* cb2 = (const float*)d_in[9];
    const float* cw3 = (const float*)d_in[10];
    const float* cb3 = (const float*)d_in[11];
    float* out = (float*)d_out;

    group_kernel<<<1, 256>>>(gi);
    fc1_kernel<<<NTILES, 256>>>(z, W1, b1);
    fc2_kernel<<<dim3(NTILES, 7), 256>>>(W2, b2);
    cudaFuncSetAttribute(conv_kernel,
                         cudaFuncAttributeMaxDynamicSharedMemorySize,
                         SM_TOTALF * 4);
    conv_kernel<<<BATCH, 256, SM_TOTALF * 4>>>(gi, cw1, cb1, cw2, cb2,
                                               cw3, cb3, out);
}

// round 2
// speedup vs baseline: 1.1877x; 1.1877x over previous
#include <cuda_runtime.h>
#include <math.h>

#define BATCH 2048
#define NZ 128
#define NGEN 8
#define TS 16
#define NTILES 136   // ceil((2048 + 8*15)/16)

// ---------------- device scratch (no allocations allowed) ----------------
__device__ float d_h1[BATCH * 256];     // FC1 output
__device__ float d_h2[BATCH * 1568];    // FC2 output (conv input)
__device__ int   d_perm[NTILES * TS];   // samples grouped by generator, -1 padded
__device__ int   d_tileg[NTILES];       // generator per tile, -1 = empty

__device__ __forceinline__ float lrelu(float x) { return x > 0.f ? x : 0.2f * x; }

// ---------------- K0: group samples by generator into padded 16-tiles ----
__global__ void group_kernel(const int* __restrict__ g_idx) {
    __shared__ int cnt[NGEN], base[NGEN], cur[NGEN];
    int tid = threadIdx.x;
    if (tid < NGEN) { cnt[tid] = 0; cur[tid] = 0; }
    __syncthreads();
    for (int b = tid; b < BATCH; b += blockDim.x)
        atomicAdd(&cnt[g_idx[b]], 1);
    for (int i = tid; i < NTILES * TS; i += blockDim.x)
        d_perm[i] = -1;
    __syncthreads();
    if (tid == 0) {
        int off = 0;
        for (int g = 0; g < NGEN; g++) {
            base[g] = off;
            off += ((cnt[g] + TS - 1) / TS) * TS;
        }
    }
    __syncthreads();
    for (int b = tid; b < BATCH; b += blockDim.x) {
        int g = g_idx[b];
        int p = atomicAdd(&cur[g], 1);
        d_perm[base[g] + p] = b;
    }
    for (int t = tid; t < NTILES; t += blockDim.x) {
        int start = t * TS, gg = -1;
        for (int g = 0; g < NGEN; g++) {
            int padded = ((cnt[g] + TS - 1) / TS) * TS;
            if (start >= base[g] && start < base[g] + padded) gg = g;
        }
        d_tileg[t] = gg;
    }
}

// ---------------- K1: FC1  h1 = lrelu(z @ W1[g] + b1[g]) ------------------
// s = tid&15 (sample), c = tid>>4 (output slice): half-warp shares c ->
// 16-way LDS broadcast on weights; z reads stride-130 conflict-free.
__global__ void __launch_bounds__(256) fc1_kernel(
    const float* __restrict__ z, const float* __restrict__ W1,
    const float* __restrict__ b1)
{
    int t = blockIdx.x;
    int g = d_tileg[t];
    if (g < 0) return;
    __shared__ int sids[TS];
    __shared__ float zsm[TS * 130];
    __shared__ __align__(16) float wst[16 * 256];
    int tid = threadIdx.x;
    if (tid < TS) sids[tid] = d_perm[t * TS + tid];
    __syncthreads();
    for (int i = tid; i < TS * NZ; i += 256) {
        int s = i >> 7, k = i & 127;
        int b = sids[s];
        zsm[s * 130 + k] = (b >= 0) ? z[b * NZ + k] : 0.f;
    }
    int s = tid & 15, c = tid >> 4;
    float acc[16];
#pragma unroll
    for (int j = 0; j < 16; j++) acc[j] = 0.f;
    const float* Wg = W1 + (size_t)g * NZ * 256;
    for (int kc = 0; kc < 8; kc++) {
        __syncthreads();
#pragma unroll
        for (int j = 0; j < 16; j++) {
            int idx = tid + 256 * j;
            wst[idx] = Wg[(kc * 16 + (idx >> 8)) * 256 + (idx & 255)];
        }
        __syncthreads();
#pragma unroll
        for (int k = 0; k < 16; k++) {
            float zv = zsm[s * 130 + kc * 16 + k];
            const float4* wp = (const float4*)&wst[k * 256 + c * 16];
#pragma unroll
            for (int j = 0; j < 4; j++) {
                float4 w = wp[j];
                acc[4 * j + 0] += zv * w.x;
                acc[4 * j + 1] += zv * w.y;
                acc[4 * j + 2] += zv * w.z;
                acc[4 * j + 3] += zv * w.w;
            }
        }
    }
    int b = sids[s];
    if (b >= 0) {
#pragma unroll
        for (int j = 0; j < 16; j++)
            acc[j] = lrelu(acc[j] + b1[g * 256 + c * 16 + j]);
        float4* dst = (float4*)&d_h1[b * 256 + c * 16];
#pragma unroll
        for (int j = 0; j < 4; j++)
            dst[j] = make_float4(acc[4 * j], acc[4 * j + 1], acc[4 * j + 2], acc[4 * j + 3]);
    }
}

// ---------------- K2: FC2  h2 = lrelu(h1 @ W2[g] + b2[g]) -----------------
__global__ void __launch_bounds__(256) fc2_kernel(
    const float* __restrict__ W2, const float* __restrict__ b2)
{
    int t = blockIdx.x, q = blockIdx.y;
    int g = d_tileg[t];
    if (g < 0) return;
    __shared__ int sids[TS];
    __shared__ float h1sm[TS * 257];
    __shared__ __align__(8) float wst[16 * 224];
    int tid = threadIdx.x;
    if (tid < TS) sids[tid] = d_perm[t * TS + tid];
    __syncthreads();
    for (int i = tid; i < TS * 256; i += 256) {
        int s = i >> 8, k = i & 255;
        int b = sids[s];
        h1sm[s * 257 + k] = (b >= 0) ? d_h1[b * 256 + k] : 0.f;
    }
    int s = tid & 15, c = tid >> 4;
    float acc[14];
#pragma unroll
    for (int j = 0; j < 14; j++) acc[j] = 0.f;
    const float* Wg = W2 + (size_t)g * 256 * 1568 + q * 224;
    for (int kc = 0; kc < 16; kc++) {
        __syncthreads();
#pragma unroll
        for (int j = 0; j < 14; j++) {
            int idx = tid + 256 * j;
            int row = idx / 224, col = idx - row * 224;
            wst[idx] = Wg[(kc * 16 + row) * 1568 + col];
        }
        __syncthreads();
#pragma unroll
        for (int k = 0; k < 16; k++) {
            float hv = h1sm[s * 257 + kc * 16 + k];
            const float2* wp = (const float2*)&wst[k * 224 + c * 14];
#pragma unroll
            for (int j = 0; j < 7; j++) {
                float2 w = wp[j];
                acc[2 * j + 0] += hv * w.x;
                acc[2 * j + 1] += hv * w.y;
            }
        }
    }
    int b = sids[s];
    if (b >= 0) {
#pragma unroll
        for (int j = 0; j < 14; j++) {
            int o = q * 224 + c * 14 + j;
            d_h2[(size_t)b * 1568 + o] = lrelu(acc[j] + b2[g * 1568 + o]);
        }
    }
}

// ---------------- K3: conv chain, one CTA per sample ----------------------
// Shared-memory layout (floats), aliasing x1 inside x3's region since they
// are never simultaneously live:
//   x2 : [0,     4096)   16 x 16 x 16 padded
//   x3 : [4096, 11296)   8 x 30 x 30 padded
//   x1 : [4096,  6688)   32 x 9 x 9 padded   (dead before x3 is written)
//   wb : [11296,13472)   weight stage: cw1 quarters (2048) / cw2(2048)+cw3(72)
#define SM_X2 0
#define SM_X3 4096
#define SM_X1 4096
#define SM_WB 11296
#define SM_TOTALF 13472

__global__ void __launch_bounds__(256, 3) conv_kernel(
    const int* __restrict__ g_idx,
    const float* __restrict__ cw1, const float* __restrict__ cb1,
    const float* __restrict__ cw2, const float* __restrict__ cb2,
    const float* __restrict__ cw3, const float* __restrict__ cb3,
    float* __restrict__ out)
{
    extern __shared__ float sm[];
    int b = blockIdx.x;
    int g = g_idx[b];
    int tid = threadIdx.x;
    float* x1 = sm + SM_X1;
    float* x2 = sm + SM_X2;
    float* x3 = sm + SM_X3;
    float* wb = sm + SM_WB;

    // zero x2 + x1 regions [0, 6688)
    for (int i = tid; i < 6688; i += 256) sm[i] = 0.f;
    __syncthreads();
    // load conv input [32,7,7] into padded x1 interior
    for (int i = tid; i < 1568; i += 256) {
        int ci = i / 49, r = (i / 7) % 7, cc = i % 7;
        x1[(ci * 9 + r + 1) * 9 + cc + 1] = d_h2[(size_t)b * 1568 + i];
    }

    // ---- convT1: [32,7,7] -> [16,14,14], cw1 staged in 4 quarters ----
    int cls = tid / 56;
    int py = cls >> 1, px = cls & 1;
    int v = tid - cls * 56;
    int cob = v / 7, my = v - cob * 7;
    int co = cob * 2;
    float a0[7], a1[7];
#pragma unroll
    for (int m = 0; m < 7; m++) { a0[m] = 0.f; a1[m] = 0.f; }

    for (int qc = 0; qc < 4; qc++) {
        __syncthreads();
        // stage cw1[ci = 8qc .. 8qc+7] -> [ci][jy][jx][co16]
        for (int i = tid; i < 2048; i += 256) {
            int ci = i >> 8, cc = (i >> 4) & 15, jy = (i >> 2) & 3, jx = i & 3;
            wb[((ci * 4 + jy) * 4 + jx) * 16 + cc] = cw1[g * 8192 + qc * 2048 + i];
        }
        __syncthreads();
        if (tid < 224) {
            for (int ci = 0; ci < 8; ci++) {
                int cig = qc * 8 + ci;
#pragma unroll
                for (int d = 0; d < 2; d++) {
                    int jy = (1 - py) + 2 * d;
                    const float* xr = &x1[(cig * 9 + my + 1 + py - d) * 9];
#pragma unroll
                    for (int e = 0; e < 2; e++) {
                        int jx = (1 - px) + 2 * e;
                        const float* wp = &wb[((ci * 4 + jy) * 4 + jx) * 16 + co];
                        float w0 = wp[0], w1 = wp[1];
                        const float* xp = xr + 1 + px - e;
#pragma unroll
                        for (int m = 0; m < 7; m++) {
                            float xv = xp[m];
                            a0[m] += w0 * xv;
                            a1[m] += w1 * xv;
                        }
                    }
                }
            }
        }
    }
    if (tid < 224) {
        float bb0 = cb1[g * 16 + co], bb1 = cb1[g * 16 + co + 1];
        int oy = 2 * my + py;
#pragma unroll
        for (int m = 0; m < 7; m++) {
            int ox = 2 * m + px;
            x2[(co * 16 + oy + 1) * 16 + ox + 1] = lrelu(a0[m] + bb0);
            x2[((co + 1) * 16 + oy + 1) * 16 + ox + 1] = lrelu(a1[m] + bb1);
        }
    }
    __syncthreads();     // convT1 writes done; x1 now dead

    // zero x3 region, stage cw2 -> [ci][jy][jx][co8], cw3 -> wb+2048
    for (int i = tid; i < 7200; i += 256) x3[i] = 0.f;
    for (int i = tid; i < 2048; i += 256) {
        int ci = i >> 7, cc = (i >> 4) & 7, jy = (i >> 2) & 3, jx = i & 3;
        wb[((ci * 4 + jy) * 4 + jx) * 8 + cc] = cw2[g * 2048 + i];
    }
    if (tid < 72) wb[2048 + tid] = cw3[g * 72 + tid];
    __syncthreads();

    // ---- convT2: [16,14,14] -> [8,28,28] ----
    if (tid < 224) {
        int v2 = tid - cls * 56;
        int cob2 = v2 / 14, my2 = v2 - cob2 * 14;
        int co2 = cob2 * 2;
        float c0[14], c1[14];
#pragma unroll
        for (int m = 0; m < 14; m++) { c0[m] = 0.f; c1[m] = 0.f; }
        for (int ci = 0; ci < 16; ci++) {
#pragma unroll
            for (int d = 0; d < 2; d++) {
                int jy = (1 - py) + 2 * d;
                const float* xr = &x2[(ci * 16 + my2 + 1 + py - d) * 16];
#pragma unroll
                for (int e = 0; e < 2; e++) {
                    int jx = (1 - px) + 2 * e;
                    const float* wp = &wb[((ci * 4 + jy) * 4 + jx) * 8 + co2];
                    float w0 = wp[0], w1 = wp[1];
                    const float* xp = xr + 1 + px - e;
#pragma unroll
                    for (int m = 0; m < 14; m++) {
                        float xv = xp[m];
                        c0[m] += w0 * xv;
                        c1[m] += w1 * xv;
                    }
                }
            }
        }
        float bb0 = cb2[g * 8 + co2], bb1 = cb2[g * 8 + co2 + 1];
        int oy = 2 * my2 + py;
#pragma unroll
        for (int m = 0; m < 14; m++) {
            int ox = 2 * m + px;
            x3[(co2 * 30 + oy + 1) * 30 + ox + 1] = lrelu(c0[m] + bb0);
            x3[((co2 + 1) * 30 + oy + 1) * 30 + ox + 1] = lrelu(c1[m] + bb1);
        }
    }
    __syncthreads();

    // ---- convT3 (stride1 k3 p1): [8,28,28] -> [1,28,28], tanh ----
    float bb = cb3[g];
    for (int p = tid; p < 784; p += 256) {
        int oy = p / 28, ox = p - oy * 28;
        float acc = bb;
#pragma unroll
        for (int ci = 0; ci < 8; ci++) {
#pragma unroll
            for (int jy = 0; jy < 3; jy++) {
                const float* xr = &x3[(ci * 30 + oy + 2 - jy) * 30 + ox];
                const float* wr = &wb[2048 + ci * 9 + jy * 3];
                acc += xr[2] * wr[0] + xr[1] * wr[1] + xr[0] * wr[2];
            }
        }
        out[(size_t)b * 784 + p] = tanhf(acc);
    }
}

// ---------------- launch ----------------
extern "C" void kernel_launch(void* const* d_in, const int* in_sizes, int n_in,
                              void* d_out, int out_size)
{
    (void)in_sizes; (void)n_in; (void)out_size;
    const float* z   = (const float*)d_in[0];
    const int*   gi  = (const int*)d_in[1];
    const float* W1  = (const float*)d_in[2];
    const float* b1  = (const float*)d_in[3];
    const float* W2  = (const float*)d_in[4];
    const float* b2  = (const float*)d_in[5];
    const float* cw1 = (const float*)d_in[6];
    const float* cb1 = (const float*)d_in[7];
    const float* cw2 = (const float*)d_in[8];
    const float* cb2 = (const float*)d_in[9];
    const float* cw3 = (const float*)d_in[10];
    const float* cb3 = (const float*)d_in[11];
    float* out = (float*)d_out;

    group_kernel<<<1, 256>>>(gi);
    fc1_kernel<<<NTILES, 256>>>(z, W1, b1);
    fc2_kernel<<<dim3(NTILES, 7), 256>>>(W2, b2);
    cudaFuncSetAttribute(conv_kernel,
                         cudaFuncAttributeMaxDynamicSharedMemorySize,
                         SM_TOTALF * 4);
    conv_kernel<<<BATCH, 256, SM_TOTALF * 4>>>(gi, cw1, cb1, cw2, cb2,
                                               cw3, cb3, out);
}

// round 3
// speedup vs baseline: 1.3875x; 1.1683x over previous
#include <cuda_runtime.h>
#include <math.h>

#define BATCH 2048
#define NZ 128
#define NGEN 8
#define TS 16
#define NTILES 136   // ceil((2048 + 8*15)/16)

// ---------------- device scratch (no allocations allowed) ----------------
__device__ float d_h1[BATCH * 256];     // FC1 output
__device__ float d_h2[BATCH * 1568];    // FC2 output (conv input)
__device__ int   d_perm[NTILES * TS];   // samples grouped by generator, -1 padded
__device__ int   d_tileg[NTILES];       // generator per tile, -1 = empty

__device__ __forceinline__ float lrelu(float x) { return x > 0.f ? x : 0.2f * x; }

// ---------------- K0: group samples by generator into padded 16-tiles ----
__global__ void group_kernel(const int* __restrict__ g_idx) {
    __shared__ int cnt[NGEN], base[NGEN], cur[NGEN];
    int tid = threadIdx.x;
    if (tid < NGEN) { cnt[tid] = 0; cur[tid] = 0; }
    __syncthreads();
    for (int b = tid; b < BATCH; b += blockDim.x)
        atomicAdd(&cnt[g_idx[b]], 1);
    for (int i = tid; i < NTILES * TS; i += blockDim.x)
        d_perm[i] = -1;
    __syncthreads();
    if (tid == 0) {
        int off = 0;
        for (int g = 0; g < NGEN; g++) {
            base[g] = off;
            off += ((cnt[g] + TS - 1) / TS) * TS;
        }
    }
    __syncthreads();
    for (int b = tid; b < BATCH; b += blockDim.x) {
        int g = g_idx[b];
        int p = atomicAdd(&cur[g], 1);
        d_perm[base[g] + p] = b;
    }
    for (int t = tid; t < NTILES; t += blockDim.x) {
        int start = t * TS, gg = -1;
        for (int g = 0; g < NGEN; g++) {
            int padded = ((cnt[g] + TS - 1) / TS) * TS;
            if (start >= base[g] && start < base[g] + padded) gg = g;
        }
        d_tileg[t] = gg;
    }
}

// ---------------- K1: FC1  h1 = lrelu(z @ W1[g] + b1[g]) ------------------
__global__ void __launch_bounds__(256) fc1_kernel(
    const float* __restrict__ z, const float* __restrict__ W1,
    const float* __restrict__ b1)
{
    int t = blockIdx.x;
    int g = d_tileg[t];
    if (g < 0) return;
    __shared__ int sids[TS];
    __shared__ float zsm[TS * 130];
    __shared__ __align__(16) float wst[16 * 256];
    int tid = threadIdx.x;
    if (tid < TS) sids[tid] = d_perm[t * TS + tid];
    __syncthreads();
    for (int i = tid; i < TS * NZ; i += 256) {
        int s = i >> 7, k = i & 127;
        int b = sids[s];
        zsm[s * 130 + k] = (b >= 0) ? z[b * NZ + k] : 0.f;
    }
    int s = tid & 15, c = tid >> 4;
    float acc[16];
#pragma unroll
    for (int j = 0; j < 16; j++) acc[j] = 0.f;
    const float* Wg = W1 + (size_t)g * NZ * 256;
    for (int kc = 0; kc < 8; kc++) {
        __syncthreads();
#pragma unroll
        for (int j = 0; j < 16; j++) {
            int idx = tid + 256 * j;
            wst[idx] = Wg[(kc * 16 + (idx >> 8)) * 256 + (idx & 255)];
        }
        __syncthreads();
#pragma unroll
        for (int k = 0; k < 16; k++) {
            float zv = zsm[s * 130 + kc * 16 + k];
            const float4* wp = (const float4*)&wst[k * 256 + c * 16];
#pragma unroll
            for (int j = 0; j < 4; j++) {
                float4 w = wp[j];
                acc[4 * j + 0] += zv * w.x;
                acc[4 * j + 1] += zv * w.y;
                acc[4 * j + 2] += zv * w.z;
                acc[4 * j + 3] += zv * w.w;
            }
        }
    }
    int b = sids[s];
    if (b >= 0) {
#pragma unroll
        for (int j = 0; j < 16; j++)
            acc[j] = lrelu(acc[j] + b1[g * 256 + c * 16 + j]);
        float4* dst = (float4*)&d_h1[b * 256 + c * 16];
#pragma unroll
        for (int j = 0; j < 4; j++)
            dst[j] = make_float4(acc[4 * j], acc[4 * j + 1], acc[4 * j + 2], acc[4 * j + 3]);
    }
}

// ---------------- K2: FC2  h2 = lrelu(h1 @ W2[g] + b2[g]) -----------------
// 224 threads: s = tid&15 (sample), c = tid>>4 in 0..13, 28 outputs/thread.
// Weight reads are float4 with only 2 unique addresses per warp (broadcast).
__global__ void __launch_bounds__(224) fc2_kernel(
    const float* __restrict__ W2, const float* __restrict__ b2)
{
    int t = blockIdx.x, q = blockIdx.y;   // q in 0..3, 392 outputs per q
    int g = d_tileg[t];
    if (g < 0) return;
    __shared__ int sids[TS];
    __shared__ float h1sm[TS * 257];
    __shared__ __align__(16) float wst[16 * 392];
    int tid = threadIdx.x;
    if (tid < TS) sids[tid] = d_perm[t * TS + tid];
    __syncthreads();
    for (int i = tid; i < TS * 256; i += 224) {
        int s = i >> 8, k = i & 255;
        int b = sids[s];
        h1sm[s * 257 + k] = (b >= 0) ? d_h1[b * 256 + k] : 0.f;
    }
    int s = tid & 15, c = tid >> 4;
    float acc[28];
#pragma unroll
    for (int j = 0; j < 28; j++) acc[j] = 0.f;
    const float* Wg = W2 + (size_t)g * 256 * 1568 + q * 392;
    for (int kc = 0; kc < 16; kc++) {
        __syncthreads();
#pragma unroll
        for (int j = 0; j < 28; j++) {
            int i = tid + 224 * j;
            int row = i / 392, col = i - row * 392;
            wst[i] = Wg[(kc * 16 + row) * 1568 + col];
        }
        __syncthreads();
#pragma unroll
        for (int k = 0; k < 16; k++) {
            float hv = h1sm[s * 257 + kc * 16 + k];
            const float4* wp = (const float4*)&wst[k * 392 + c * 28];
#pragma unroll
            for (int j = 0; j < 7; j++) {
                float4 w = wp[j];
                acc[4 * j + 0] += hv * w.x;
                acc[4 * j + 1] += hv * w.y;
                acc[4 * j + 2] += hv * w.z;
                acc[4 * j + 3] += hv * w.w;
            }
        }
    }
    int b = sids[s];
    if (b >= 0) {
        float4* dst = (float4*)&d_h2[(size_t)b * 1568 + q * 392 + c * 28];
        const float* bp = b2 + g * 1568 + q * 392 + c * 28;
#pragma unroll
        for (int j = 0; j < 7; j++) {
            float4 v;
            v.x = lrelu(acc[4 * j + 0] + bp[4 * j + 0]);
            v.y = lrelu(acc[4 * j + 1] + bp[4 * j + 1]);
            v.z = lrelu(acc[4 * j + 2] + bp[4 * j + 2]);
            v.w = lrelu(acc[4 * j + 3] + bp[4 * j + 3]);
            dst[j] = v;
        }
    }
}

// ---------------- K3: conv chain, one CTA per sample ----------------------
// smem (floats):
//   x2 : [0, 4096)        16 x 16 x 16 padded
//   x3 : [4096, 11776)    8 x 30 x 32 padded (stride 32 for float4 rows)
//   x1 : [4096, 7552)     32 x 9 x 12 padded (aliases x3; dead before x3)
//   wb : [11776, 13896)   2048 weight stage + 72 (cw3)
#define SM_X2 0
#define SM_X3 4096
#define SM_X1 4096
#define SM_WB 11776
#define SM_TOTALF 13896

// convT1 parity-class compute over one 8-ci weight quarter. PX compile-time
// so register-row indexing is static.
template<int PX>
__device__ __forceinline__ void convt1_quarter(
    const float* __restrict__ x1q, const float* __restrict__ wb,
    int my, int py, int co, float* a0, float* a1)
{
    for (int ci = 0; ci < 8; ci++) {
        const float* xc = x1q + ci * 108;           // 9*12
#pragma unroll
        for (int d = 0; d < 2; d++) {
            int row = my + py + 1 - d;
            float r[12];
            const float4* rp = (const float4*)(xc + row * 12);
#pragma unroll
            for (int tt = 0; tt < 3; tt++) {
                float4 vv = rp[tt];
                r[4 * tt] = vv.x; r[4 * tt + 1] = vv.y;
                r[4 * tt + 2] = vv.z; r[4 * tt + 3] = vv.w;
            }
            int jy = 1 - py + 2 * d;
#pragma unroll
            for (int e = 0; e < 2; e++) {
                int jx = 1 - PX + 2 * e;
                float2 w = *(const float2*)&wb[((ci * 4 + jy) * 4 + jx) * 16 + co];
#pragma unroll
                for (int m = 0; m < 7; m++) {
                    float xv = r[1 + PX - e + m];
                    a0[m] += w.x * xv;
                    a1[m] += w.y * xv;
                }
            }
        }
    }
}

template<int PX>
__device__ __forceinline__ void convt2_compute(
    const float* __restrict__ x2, const float* __restrict__ wb,
    int my, int py, int co, float* c0, float* c1)
{
    for (int ci = 0; ci < 16; ci++) {
        const float* xc = x2 + ci * 256;            // 16*16
#pragma unroll
        for (int d = 0; d < 2; d++) {
            int row = my + py + 1 - d;
            float r[16];
            const float4* rp = (const float4*)(xc + row * 16);
#pragma unroll
            for (int tt = 0; tt < 4; tt++) {
                float4 vv = rp[tt];
                r[4 * tt] = vv.x; r[4 * tt + 1] = vv.y;
                r[4 * tt + 2] = vv.z; r[4 * tt + 3] = vv.w;
            }
            int jy = 1 - py + 2 * d;
#pragma unroll
            for (int e = 0; e < 2; e++) {
                int jx = 1 - PX + 2 * e;
                float2 w = *(const float2*)&wb[((ci * 4 + jy) * 4 + jx) * 8 + co];
#pragma unroll
                for (int m = 0; m < 14; m++) {
                    float xv = r[1 + PX - e + m];
                    c0[m] += w.x * xv;
                    c1[m] += w.y * xv;
                }
            }
        }
    }
}

// convT3: thread handles 7 consecutive ox; OFF = seg*7 - 4*B4 (static).
template<int OFF>
__device__ __forceinline__ void convt3_compute(
    const float* __restrict__ x3, const float* __restrict__ w3,
    int oy, int b4, float* acc)
{
    for (int ci = 0; ci < 8; ci++) {
#pragma unroll
        for (int jy = 0; jy < 3; jy++) {
            int row = oy + 2 - jy;
            float r[12];
            const float4* rp = (const float4*)&x3[(ci * 30 + row) * 32] + b4;
#pragma unroll
            for (int tt = 0; tt < 3; tt++) {
                float4 vv = rp[tt];
                r[4 * tt] = vv.x; r[4 * tt + 1] = vv.y;
                r[4 * tt + 2] = vv.z; r[4 * tt + 3] = vv.w;
            }
            const float* wr = w3 + ci * 9 + jy * 3;
#pragma unroll
            for (int jx = 0; jx < 3; jx++) {
                float wv = wr[jx];
#pragma unroll
                for (int u = 0; u < 7; u++)
                    acc[u] += wv * r[OFF + u + 2 - jx];
            }
        }
    }
}

__global__ void __launch_bounds__(256, 3) conv_kernel(
    const int* __restrict__ g_idx,
    const float* __restrict__ cw1, const float* __restrict__ cb1,
    const float* __restrict__ cw2, const float* __restrict__ cb2,
    const float* __restrict__ cw3, const float* __restrict__ cb3,
    float* __restrict__ out)
{
    extern __shared__ float sm[];
    int b = blockIdx.x;
    int g = g_idx[b];
    int tid = threadIdx.x;
    float* x1 = sm + SM_X1;
    float* x2 = sm + SM_X2;
    float* x3 = sm + SM_X3;
    float* wb = sm + SM_WB;

    int cls = tid >> 6;          // warp-uniform parity class
    int py = cls >> 1, px = cls & 1;
    int v = tid & 63;

    // zero x2 + x1 regions [0, 7552)
    for (int i = tid; i < 7552; i += 256) sm[i] = 0.f;
    __syncthreads();
    // load conv input [32,7,7] into padded x1 interior (stride 12)
    for (int i = tid; i < 1568; i += 256) {
        int ci = i / 49, r = (i / 7) % 7, cc = i % 7;
        x1[ci * 108 + (r + 1) * 12 + cc + 1] = d_h2[(size_t)b * 1568 + i];
    }

    // ---- convT1: [32,7,7] -> [16,14,14], cw1 staged in 4 quarters ----
    int my1 = v >> 3, cob1 = v & 7, co1 = cob1 * 2;   // valid when v < 56
    float a0[7], a1[7];
#pragma unroll
    for (int m = 0; m < 7; m++) { a0[m] = 0.f; a1[m] = 0.f; }

    for (int qc = 0; qc < 4; qc++) {
        __syncthreads();
        for (int i = tid; i < 2048; i += 256) {
            int ci = i >> 8, cc = (i >> 4) & 15, jy = (i >> 2) & 3, jx = i & 3;
            wb[((ci * 4 + jy) * 4 + jx) * 16 + cc] = cw1[g * 8192 + qc * 2048 + i];
        }
        __syncthreads();
        if (v < 56) {
            const float* x1q = x1 + qc * 8 * 108;
            if (px == 0) convt1_quarter<0>(x1q, wb, my1, py, co1, a0, a1);
            else         convt1_quarter<1>(x1q, wb, my1, py, co1, a0, a1);
        }
    }
    if (v < 56) {
        float bb0 = cb1[g * 16 + co1], bb1 = cb1[g * 16 + co1 + 1];
        int oy = 2 * my1 + py;
#pragma unroll
        for (int m = 0; m < 7; m++) {
            int ox = 2 * m + px;
            x2[(co1 * 16 + oy + 1) * 16 + ox + 1] = lrelu(a0[m] + bb0);
            x2[((co1 + 1) * 16 + oy + 1) * 16 + ox + 1] = lrelu(a1[m] + bb1);
        }
    }
    __syncthreads();     // convT1 done; x1 dead

    // zero x3, stage cw2 -> [ci][jy][jx][co8], cw3 -> wb+2048
    for (int i = tid; i < 7680; i += 256) x3[i] = 0.f;
    for (int i = tid; i < 2048; i += 256) {
        int ci = i >> 7, cc = (i >> 4) & 7, jy = (i >> 2) & 3, jx = i & 3;
        wb[((ci * 4 + jy) * 4 + jx) * 8 + cc] = cw2[g * 2048 + i];
    }
    if (tid < 72) wb[2048 + tid] = cw3[g * 72 + tid];
    __syncthreads();

    // ---- convT2: [16,14,14] -> [8,28,28] ----
    if (v < 56) {
        int my = v >> 2, co = (v & 3) * 2;
        float c0[14], c1[14];
#pragma unroll
        for (int m = 0; m < 14; m++) { c0[m] = 0.f; c1[m] = 0.f; }
        if (px == 0) convt2_compute<0>(x2, wb, my, py, co, c0, c1);
        else         convt2_compute<1>(x2, wb, my, py, co, c0, c1);
        float bb0 = cb2[g * 8 + co], bb1 = cb2[g * 8 + co + 1];
        int oy = 2 * my + py;
#pragma unroll
        for (int m = 0; m < 14; m++) {
            int ox = 2 * m + px;
            x3[(co * 30 + oy + 1) * 32 + ox + 1] = lrelu(c0[m] + bb0);
            x3[((co + 1) * 30 + oy + 1) * 32 + ox + 1] = lrelu(c1[m] + bb1);
        }
    }
    __syncthreads();

    // ---- convT3 (stride1 k3 p1): [8,28,28] -> [1,28,28], tanh ----
    if (tid < 128) {
        int seg = tid >> 5;          // warp-uniform
        int oy = tid & 31;
        if (oy < 28) {
            float bb = cb3[g];
            float acc[7];
#pragma unroll
            for (int u = 0; u < 7; u++) acc[u] = bb;
            const float* w3 = wb + 2048;
            switch (seg) {
                case 0: convt3_compute<0>(x3, w3, oy, 0, acc); break;
                case 1: convt3_compute<3>(x3, w3, oy, 1, acc); break;
                case 2: convt3_compute<2>(x3, w3, oy, 3, acc); break;
                default: convt3_compute<1>(x3, w3, oy, 5, acc); break;
            }
            float* op = out + (size_t)b * 784 + oy * 28 + seg * 7;
#pragma unroll
            for (int u = 0; u < 7; u++) op[u] = tanhf(acc[u]);
        }
    }
}

// ---------------- launch ----------------
extern "C" void kernel_launch(void* const* d_in, const int* in_sizes, int n_in,
                              void* d_out, int out_size)
{
    (void)in_sizes; (void)n_in; (void)out_size;
    const float* z   = (const float*)d_in[0];
    const int*   gi  = (const int*)d_in[1];
    const float* W1  = (const float*)d_in[2];
    const float* b1  = (const float*)d_in[3];
    const float* W2  = (const float*)d_in[4];
    const float* b2  = (const float*)d_in[5];
    const float* cw1 = (const float*)d_in[6];
    const float* cb1 = (const float*)d_in[7];
    const float* cw2 = (const float*)d_in[8];
    const float* cb2 = (const float*)d_in[9];
    const float* cw3 = (const float*)d_in[10];
    const float* cb3 = (const float*)d_in[11];
    float* out = (float*)d_out;

    group_kernel<<<1, 256>>>(gi);
    fc1_kernel<<<NTILES, 256>>>(z, W1, b1);
    fc2_kernel<<<dim3(NTILES, 4), 224>>>(W2, b2);
    cudaFuncSetAttribute(conv_kernel,
                         cudaFuncAttributeMaxDynamicSharedMemorySize,
                         SM_TOTALF * 4);
    conv_kernel<<<BATCH, 256, SM_TOTALF * 4>>>(gi, cw1, cb1, cw2, cb2,
                                               cw3, cb3, out);
}

// round 4
// speedup vs baseline: 1.6105x; 1.1607x over previous
#include <cuda_runtime.h>
#include <math.h>

#define BATCH 2048
#define NZ 128
#define NGEN 8
#define TS 16
#define NTILES 136   // ceil((2048 + 8*15)/16)

// ---------------- device scratch (no allocations allowed) ----------------
__device__ float d_h1[BATCH * 256];     // FC1 output
__device__ float d_h2[BATCH * 1568];    // FC2 output (conv input)
__device__ int   d_perm[NTILES * TS];   // samples grouped by generator, -1 padded
__device__ int   d_tileg[NTILES];       // generator per tile, -1 = empty

__device__ __forceinline__ float lrelu(float x) { return x > 0.f ? x : 0.2f * x; }

// ---------------- K0: group samples by generator into padded 16-tiles ----
__global__ void group_kernel(const int* __restrict__ g_idx) {
    __shared__ int cnt[NGEN], base[NGEN], cur[NGEN];
    int tid = threadIdx.x;
    if (tid < NGEN) { cnt[tid] = 0; cur[tid] = 0; }
    __syncthreads();
    for (int b = tid; b < BATCH; b += blockDim.x)
        atomicAdd(&cnt[g_idx[b]], 1);
    for (int i = tid; i < NTILES * TS; i += blockDim.x)
        d_perm[i] = -1;
    __syncthreads();
    if (tid == 0) {
        int off = 0;
        for (int g = 0; g < NGEN; g++) {
            base[g] = off;
            off += ((cnt[g] + TS - 1) / TS) * TS;
        }
    }
    __syncthreads();
    for (int b = tid; b < BATCH; b += blockDim.x) {
        int g = g_idx[b];
        int p = atomicAdd(&cur[g], 1);
        d_perm[base[g] + p] = b;
    }
    for (int t = tid; t < NTILES; t += blockDim.x) {
        int start = t * TS, gg = -1;
        for (int g = 0; g < NGEN; g++) {
            int padded = ((cnt[g] + TS - 1) / TS) * TS;
            if (start >= base[g] && start < base[g] + padded) gg = g;
        }
        d_tileg[t] = gg;
    }
}

// ---------------- K1: FC1  h1 = lrelu(z @ W1[g] + b1[g]) ------------------
__global__ void __launch_bounds__(256) fc1_kernel(
    const float* __restrict__ z, const float* __restrict__ W1,
    const float* __restrict__ b1)
{
    int t = blockIdx.x;
    int g = d_tileg[t];
    if (g < 0) return;
    __shared__ int sids[TS];
    __shared__ float zsm[TS * 130];
    __shared__ __align__(16) float wst[16 * 256];
    int tid = threadIdx.x;
    if (tid < TS) sids[tid] = d_perm[t * TS + tid];
    __syncthreads();
    for (int i = tid; i < TS * NZ; i += 256) {
        int s = i >> 7, k = i & 127;
        int b = sids[s];
        zsm[s * 130 + k] = (b >= 0) ? z[b * NZ + k] : 0.f;
    }
    int s = tid & 15, c = tid >> 4;
    float acc[16];
#pragma unroll
    for (int j = 0; j < 16; j++) acc[j] = 0.f;
    const float* Wg = W1 + (size_t)g * NZ * 256;
    for (int kc = 0; kc < 8; kc++) {
        __syncthreads();
#pragma unroll
        for (int j = 0; j < 16; j++) {
            int idx = tid + 256 * j;
            wst[idx] = Wg[(kc * 16 + (idx >> 8)) * 256 + (idx & 255)];
        }
        __syncthreads();
#pragma unroll
        for (int k = 0; k < 16; k++) {
            float zv = zsm[s * 130 + kc * 16 + k];
            const float4* wp = (const float4*)&wst[k * 256 + c * 16];
#pragma unroll
            for (int j = 0; j < 4; j++) {
                float4 w = wp[j];
                acc[4 * j + 0] += zv * w.x;
                acc[4 * j + 1] += zv * w.y;
                acc[4 * j + 2] += zv * w.z;
                acc[4 * j + 3] += zv * w.w;
            }
        }
    }
    int b = sids[s];
    if (b >= 0) {
#pragma unroll
        for (int j = 0; j < 16; j++)
            acc[j] = lrelu(acc[j] + b1[g * 256 + c * 16 + j]);
        float4* dst = (float4*)&d_h1[b * 256 + c * 16];
#pragma unroll
        for (int j = 0; j < 4; j++)
            dst[j] = make_float4(acc[4 * j], acc[4 * j + 1], acc[4 * j + 2], acc[4 * j + 3]);
    }
}

// ---------------- K2: FC2  h2 = lrelu(h1 @ W2[g] + b2[g]) -----------------
__global__ void __launch_bounds__(224) fc2_kernel(
    const float* __restrict__ W2, const float* __restrict__ b2)
{
    int t = blockIdx.x, q = blockIdx.y;   // q in 0..3, 392 outputs per q
    int g = d_tileg[t];
    if (g < 0) return;
    __shared__ int sids[TS];
    __shared__ float h1sm[TS * 257];
    __shared__ __align__(16) float wst[16 * 392];
    int tid = threadIdx.x;
    if (tid < TS) sids[tid] = d_perm[t * TS + tid];
    __syncthreads();
    for (int i = tid; i < TS * 256; i += 224) {
        int s = i >> 8, k = i & 255;
        int b = sids[s];
        h1sm[s * 257 + k] = (b >= 0) ? d_h1[b * 256 + k] : 0.f;
    }
    int s = tid & 15, c = tid >> 4;
    float acc[28];
#pragma unroll
    for (int j = 0; j < 28; j++) acc[j] = 0.f;
    const float* Wg = W2 + (size_t)g * 256 * 1568 + q * 392;
    for (int kc = 0; kc < 16; kc++) {
        __syncthreads();
#pragma unroll
        for (int j = 0; j < 28; j++) {
            int i = tid + 224 * j;
            int row = i / 392, col = i - row * 392;
            wst[i] = Wg[(kc * 16 + row) * 1568 + col];
        }
        __syncthreads();
#pragma unroll
        for (int k = 0; k < 16; k++) {
            float hv = h1sm[s * 257 + kc * 16 + k];
            const float4* wp = (const float4*)&wst[k * 392 + c * 28];
#pragma unroll
            for (int j = 0; j < 7; j++) {
                float4 w = wp[j];
                acc[4 * j + 0] += hv * w.x;
                acc[4 * j + 1] += hv * w.y;
                acc[4 * j + 2] += hv * w.z;
                acc[4 * j + 3] += hv * w.w;
            }
        }
    }
    int b = sids[s];
    if (b >= 0) {
        float4* dst = (float4*)&d_h2[(size_t)b * 1568 + q * 392 + c * 28];
        const float* bp = b2 + g * 1568 + q * 392 + c * 28;
#pragma unroll
        for (int j = 0; j < 7; j++) {
            float4 v;
            v.x = lrelu(acc[4 * j + 0] + bp[4 * j + 0]);
            v.y = lrelu(acc[4 * j + 1] + bp[4 * j + 1]);
            v.z = lrelu(acc[4 * j + 2] + bp[4 * j + 2]);
            v.w = lrelu(acc[4 * j + 3] + bp[4 * j + 3]);
            dst[j] = v;
        }
    }
}

// ---------------- K3: conv chain, one CTA per sample ----------------------
// smem (floats):
//   x2 : [0, 4096)        16 x 16 x 16 padded
//   x3 : [4096, 11776)    8 x 30 x 32 padded (stride 32 for float4 rows)
//   x1 : [4096, 7552)     32 x 9 x 12 padded (aliases x3; dead before x3)
//   wb : [11776, 13896)   2048 weight stage + 72 (cw3)
// Interiors are fully overwritten -> only halos get zeroed.
#define SM_X2 0
#define SM_X3 4096
#define SM_X1 4096
#define SM_WB 11776
#define SM_TOTALF 13896

template<int PX>
__device__ __forceinline__ void convt1_quarter(
    const float* __restrict__ x1q, const float* __restrict__ wb,
    int my, int py, int co, float* a0, float* a1)
{
    for (int ci = 0; ci < 8; ci++) {
        const float* xc = x1q + ci * 108;           // 9*12
#pragma unroll
        for (int d = 0; d < 2; d++) {
            int row = my + py + 1 - d;
            float r[12];
            const float4* rp = (const float4*)(xc + row * 12);
#pragma unroll
            for (int tt = 0; tt < 3; tt++) {
                float4 vv = rp[tt];
                r[4 * tt] = vv.x; r[4 * tt + 1] = vv.y;
                r[4 * tt + 2] = vv.z; r[4 * tt + 3] = vv.w;
            }
            int jy = 1 - py + 2 * d;
#pragma unroll
            for (int e = 0; e < 2; e++) {
                int jx = 1 - PX + 2 * e;
                float2 w = *(const float2*)&wb[((ci * 4 + jy) * 4 + jx) * 16 + co];
#pragma unroll
                for (int m = 0; m < 7; m++) {
                    float xv = r[1 + PX - e + m];
                    a0[m] += w.x * xv;
                    a1[m] += w.y * xv;
                }
            }
        }
    }
}

template<int PX>
__device__ __forceinline__ void convt2_compute(
    const float* __restrict__ x2, const float* __restrict__ wb,
    int my, int py, int co, float* c0, float* c1)
{
    for (int ci = 0; ci < 16; ci++) {
        const float* xc = x2 + ci * 256;            // 16*16
#pragma unroll
        for (int d = 0; d < 2; d++) {
            int row = my + py + 1 - d;
            float r[16];
            const float4* rp = (const float4*)(xc + row * 16);
#pragma unroll
            for (int tt = 0; tt < 4; tt++) {
                float4 vv = rp[tt];
                r[4 * tt] = vv.x; r[4 * tt + 1] = vv.y;
                r[4 * tt + 2] = vv.z; r[4 * tt + 3] = vv.w;
            }
            int jy = 1 - py + 2 * d;
#pragma unroll
            for (int e = 0; e < 2; e++) {
                int jx = 1 - PX + 2 * e;
                float2 w = *(const float2*)&wb[((ci * 4 + jy) * 4 + jx) * 8 + co];
#pragma unroll
                for (int m = 0; m < 14; m++) {
                    float xv = r[1 + PX - e + m];
                    c0[m] += w.x * xv;
                    c1[m] += w.y * xv;
                }
            }
        }
    }
}

__global__ void __launch_bounds__(256, 4) conv_kernel(
    const int* __restrict__ g_idx,
    const float* __restrict__ cw1, const float* __restrict__ cb1,
    const float* __restrict__ cw2, const float* __restrict__ cb2,
    const float* __restrict__ cw3, const float* __restrict__ cb3,
    float* __restrict__ out)
{
    extern __shared__ float sm[];
    int b = blockIdx.x;
    int g = g_idx[b];
    int tid = threadIdx.x;
    float* x1 = sm + SM_X1;
    float* x2 = sm + SM_X2;
    float* x3 = sm + SM_X3;
    float* wb = sm + SM_WB;

    int cls = tid >> 6;          // warp-uniform parity class
    int py = cls >> 1, px = cls & 1;
    int v = tid & 63;

    // ---- halo-only zeroing of x1 (rows 0,8 full + cols 0,8) and x2 ----
    for (int i = tid; i < 32 * 38; i += 256) {       // x1: 38 halo elems/ci
        int ci = i / 38, k = i - ci * 38;
        int row, col;
        if (k < 12)      { row = 0; col = k; }
        else if (k < 24) { row = 8; col = k - 12; }
        else { int k2 = k - 24; row = 1 + (k2 >> 1); col = (k2 & 1) * 8; }
        x1[ci * 108 + row * 12 + col] = 0.f;
    }
    for (int i = tid; i < 16 * 60; i += 256) {       // x2: 60 halo elems/ci
        int ci = i / 60, k = i - ci * 60;
        int row, col;
        if (k < 16)      { row = 0;  col = k; }
        else if (k < 32) { row = 15; col = k - 16; }
        else { int k2 = k - 32; row = 1 + (k2 >> 1); col = (k2 & 1) * 15; }
        x2[(ci * 16 + row) * 16 + col] = 0.f;
    }
    __syncthreads();
    // load conv input [32,7,7] into padded x1 interior (stride 12)
    for (int i = tid; i < 1568; i += 256) {
        int ci = i / 49, r = (i / 7) % 7, cc = i % 7;
        x1[ci * 108 + (r + 1) * 12 + cc + 1] = d_h2[(size_t)b * 1568 + i];
    }

    // ---- convT1: [32,7,7] -> [16,14,14], cw1 staged in 4 quarters ----
    int my1 = v >> 3, cob1 = v & 7, co1 = cob1 * 2;   // valid when v < 56
    float a0[7], a1[7];
#pragma unroll
    for (int m = 0; m < 7; m++) { a0[m] = 0.f; a1[m] = 0.f; }

    for (int qc = 0; qc < 4; qc++) {
        __syncthreads();
        for (int i = tid; i < 2048; i += 256) {
            int ci = i >> 8, cc = (i >> 4) & 15, jy = (i >> 2) & 3, jx = i & 3;
            wb[((ci * 4 + jy) * 4 + jx) * 16 + cc] = cw1[g * 8192 + qc * 2048 + i];
        }
        __syncthreads();
        if (v < 56) {
            const float* x1q = x1 + qc * 8 * 108;
            if (px == 0) convt1_quarter<0>(x1q, wb, my1, py, co1, a0, a1);
            else         convt1_quarter<1>(x1q, wb, my1, py, co1, a0, a1);
        }
    }
    if (v < 56) {
        float bb0 = cb1[g * 16 + co1], bb1 = cb1[g * 16 + co1 + 1];
        int oy = 2 * my1 + py;
#pragma unroll
        for (int m = 0; m < 7; m++) {
            int ox = 2 * m + px;
            x2[(co1 * 16 + oy + 1) * 16 + ox + 1] = lrelu(a0[m] + bb0);
            x2[((co1 + 1) * 16 + oy + 1) * 16 + ox + 1] = lrelu(a1[m] + bb1);
        }
    }
    __syncthreads();     // convT1 done; x1 dead

    // halo-zero x3 (rows 0,29 cols 0..29 + cols 0,29), stage cw2 + cw3
    for (int i = tid; i < 8 * 116; i += 256) {
        int ci = i / 116, k = i - ci * 116;
        int row, col;
        if (k < 30)      { row = 0;  col = k; }
        else if (k < 60) { row = 29; col = k - 30; }
        else { int k2 = k - 60; row = 1 + (k2 >> 1); col = (k2 & 1) * 29; }
        x3[(ci * 30 + row) * 32 + col] = 0.f;
    }
    for (int i = tid; i < 2048; i += 256) {
        int ci = i >> 7, cc = (i >> 4) & 7, jy = (i >> 2) & 3, jx = i & 3;
        wb[((ci * 4 + jy) * 4 + jx) * 8 + cc] = cw2[g * 2048 + i];
    }
    if (tid < 72) wb[2048 + tid] = cw3[g * 72 + tid];
    __syncthreads();

    // ---- convT2: [16,14,14] -> [8,28,28] ----
    if (v < 56) {
        int my = v >> 2, co = (v & 3) * 2;
        float c0[14], c1[14];
#pragma unroll
        for (int m = 0; m < 14; m++) { c0[m] = 0.f; c1[m] = 0.f; }
        if (px == 0) convt2_compute<0>(x2, wb, my, py, co, c0, c1);
        else         convt2_compute<1>(x2, wb, my, py, co, c0, c1);
        float bb0 = cb2[g * 8 + co], bb1 = cb2[g * 8 + co + 1];
        int oy = 2 * my + py;
#pragma unroll
        for (int m = 0; m < 14; m++) {
            int ox = 2 * m + px;
            x3[(co * 30 + oy + 1) * 32 + ox + 1] = lrelu(c0[m] + bb0);
            x3[((co + 1) * 30 + oy + 1) * 32 + ox + 1] = lrelu(c1[m] + bb1);
        }
    }
    __syncthreads();

    // ---- convT3 (stride1 k3 p1): [8,28,28] -> [1,28,28], tanh ----
    // 196 threads: tid = oy*7 + seg, seg = 4-wide output segment.
    if (tid < 196) {
        int oy = tid / 7, s = tid - oy * 7;      // s in 0..6
        float bb = cb3[g];
        float acc[4];
#pragma unroll
        for (int u = 0; u < 4; u++) acc[u] = bb;
        const float* w3 = wb + 2048;
        for (int ci = 0; ci < 8; ci++) {
#pragma unroll
            for (int jy = 0; jy < 3; jy++) {
                int row = oy + 2 - jy;
                float r[8];
                const float4* rp = (const float4*)&x3[(ci * 30 + row) * 32 + s * 4];
#pragma unroll
                for (int tt = 0; tt < 2; tt++) {
                    float4 vv = rp[tt];
                    r[4 * tt] = vv.x; r[4 * tt + 1] = vv.y;
                    r[4 * tt + 2] = vv.z; r[4 * tt + 3] = vv.w;
                }
                const float* wr = w3 + ci * 9 + jy * 3;
#pragma unroll
                for (int jx = 0; jx < 3; jx++) {
                    float wv = wr[jx];
#pragma unroll
                    for (int u = 0; u < 4; u++)
                        acc[u] += wv * r[u + 2 - jx];
                }
            }
        }
        float4 o;
        o.x = tanhf(acc[0]); o.y = tanhf(acc[1]);
        o.z = tanhf(acc[2]); o.w = tanhf(acc[3]);
        *(float4*)(out + (size_t)b * 784 + oy * 28 + s * 4) = o;
    }
}

// ---------------- launch ----------------
extern "C" void kernel_launch(void* const* d_in, const int* in_sizes, int n_in,
                              void* d_out, int out_size)
{
    (void)in_sizes; (void)n_in; (void)out_size;
    const float* z   = (const float*)d_in[0];
    const int*   gi  = (const int*)d_in[1];
    const float* W1  = (const float*)d_in[2];
    const float* b1  = (const float*)d_in[3];
    const float* W2  = (const float*)d_in[4];
    const float* b2  = (const float*)d_in[5];
    const float* cw1 = (const float*)d_in[6];
    const float* cb1 = (const float*)d_in[7];
    const float* cw2 = (const float*)d_in[8];
    const float* cb2 = (const float*)d_in[9];
    const float* cw3 = (const float*)d_in[10];
    const float* cb3 = (const float*)d_in[11];
    float* out = (float*)d_out;

    group_kernel<<<1, 256>>>(gi);
    fc1_kernel<<<NTILES, 256>>>(z, W1, b1);
    fc2_kernel<<<dim3(NTILES, 4), 224>>>(W2, b2);
    cudaFuncSetAttribute(conv_kernel,
                         cudaFuncAttributeMaxDynamicSharedMemorySize,
                         SM_TOTALF * 4);
    conv_kernel<<<BATCH, 256, SM_TOTALF * 4>>>(gi, cw1, cb1, cw2, cb2,
                                               cw3, cb3, out);
}

// round 5
// speedup vs baseline: 1.8996x; 1.1795x over previous
#include <cuda_runtime.h>
#include <math.h>

#define BATCH 2048
#define NZ 128
#define NGEN 8
#define TS 16
#define NTILES 136   // ceil((2048 + 8*15)/16)

// ---------------- device scratch (no allocations allowed) ----------------
__device__ float d_h1[BATCH * 256];     // FC1 output
__device__ float d_h2[BATCH * 1568];    // FC2 output (conv input)
__device__ int   d_perm[NTILES * TS];   // samples grouped by generator, -1 padded
__device__ int   d_tileg[NTILES];       // generator per tile, -1 = empty

__device__ __forceinline__ float lrelu(float x) { return x > 0.f ? x : 0.2f * x; }

// ---------------- K0: group samples by generator into padded 16-tiles ----
__global__ void group_kernel(const int* __restrict__ g_idx) {
    __shared__ int cnt[NGEN], base[NGEN], cur[NGEN];
    int tid = threadIdx.x;
    if (tid < NGEN) { cnt[tid] = 0; cur[tid] = 0; }
    __syncthreads();
    for (int b = tid; b < BATCH; b += blockDim.x)
        atomicAdd(&cnt[g_idx[b]], 1);
    for (int i = tid; i < NTILES * TS; i += blockDim.x)
        d_perm[i] = -1;
    __syncthreads();
    if (tid == 0) {
        int off = 0;
        for (int g = 0; g < NGEN; g++) {
            base[g] = off;
            off += ((cnt[g] + TS - 1) / TS) * TS;
        }
    }
    __syncthreads();
    for (int b = tid; b < BATCH; b += blockDim.x) {
        int g = g_idx[b];
        int p = atomicAdd(&cur[g], 1);
        d_perm[base[g] + p] = b;
    }
    for (int t = tid; t < NTILES; t += blockDim.x) {
        int start = t * TS, gg = -1;
        for (int g = 0; g < NGEN; g++) {
            int padded = ((cnt[g] + TS - 1) / TS) * TS;
            if (start >= base[g] && start < base[g] + padded) gg = g;
        }
        d_tileg[t] = gg;
    }
}

// ---------------- K1: FC1  h1 = lrelu(z @ W1[g] + b1[g]) ------------------
__global__ void __launch_bounds__(256) fc1_kernel(
    const float* __restrict__ z, const float* __restrict__ W1,
    const float* __restrict__ b1)
{
    int t = blockIdx.x;
    int g = d_tileg[t];
    if (g < 0) return;
    __shared__ int sids[TS];
    __shared__ float zsm[TS * 130];
    __shared__ __align__(16) float wst[16 * 256];
    int tid = threadIdx.x;
    if (tid < TS) sids[tid] = d_perm[t * TS + tid];
    __syncthreads();
    for (int i = tid; i < TS * NZ; i += 256) {
        int s = i >> 7, k = i & 127;
        int b = sids[s];
        zsm[s * 130 + k] = (b >= 0) ? z[b * NZ + k] : 0.f;
    }
    int s = tid & 15, c = tid >> 4;
    float acc[16];
#pragma unroll
    for (int j = 0; j < 16; j++) acc[j] = 0.f;
    const float* Wg = W1 + (size_t)g * NZ * 256;
    for (int kc = 0; kc < 8; kc++) {
        __syncthreads();
#pragma unroll
        for (int j = 0; j < 16; j++) {
            int idx = tid + 256 * j;
            wst[idx] = Wg[(kc * 16 + (idx >> 8)) * 256 + (idx & 255)];
        }
        __syncthreads();
#pragma unroll
        for (int k = 0; k < 16; k++) {
            float zv = zsm[s * 130 + kc * 16 + k];
            const float4* wp = (const float4*)&wst[k * 256 + c * 16];
#pragma unroll
            for (int j = 0; j < 4; j++) {
                float4 w = wp[j];
                acc[4 * j + 0] += zv * w.x;
                acc[4 * j + 1] += zv * w.y;
                acc[4 * j + 2] += zv * w.z;
                acc[4 * j + 3] += zv * w.w;
            }
        }
    }
    int b = sids[s];
    if (b >= 0) {
#pragma unroll
        for (int j = 0; j < 16; j++)
            acc[j] = lrelu(acc[j] + b1[g * 256 + c * 16 + j]);
        float4* dst = (float4*)&d_h1[b * 256 + c * 16];
#pragma unroll
        for (int j = 0; j < 4; j++)
            dst[j] = make_float4(acc[4 * j], acc[4 * j + 1], acc[4 * j + 2], acc[4 * j + 3]);
    }
}

// ---------------- K2: FC2  h2 = lrelu(h1 @ W2[g] + b2[g]) -----------------
__global__ void __launch_bounds__(224) fc2_kernel(
    const float* __restrict__ W2, const float* __restrict__ b2)
{
    int t = blockIdx.x, q = blockIdx.y;   // q in 0..3, 392 outputs per q
    int g = d_tileg[t];
    if (g < 0) return;
    __shared__ int sids[TS];
    __shared__ float h1sm[TS * 257];
    __shared__ __align__(16) float wst[16 * 392];
    int tid = threadIdx.x;
    if (tid < TS) sids[tid] = d_perm[t * TS + tid];
    __syncthreads();
    for (int i = tid; i < TS * 256; i += 224) {
        int s = i >> 8, k = i & 255;
        int b = sids[s];
        h1sm[s * 257 + k] = (b >= 0) ? d_h1[b * 256 + k] : 0.f;
    }
    int s = tid & 15, c = tid >> 4;
    float acc[28];
#pragma unroll
    for (int j = 0; j < 28; j++) acc[j] = 0.f;
    const float* Wg = W2 + (size_t)g * 256 * 1568 + q * 392;
    for (int kc = 0; kc < 16; kc++) {
        __syncthreads();
#pragma unroll
        for (int j = 0; j < 28; j++) {
            int i = tid + 224 * j;
            int row = i / 392, col = i - row * 392;
            wst[i] = Wg[(kc * 16 + row) * 1568 + col];
        }
        __syncthreads();
#pragma unroll
        for (int k = 0; k < 16; k++) {
            float hv = h1sm[s * 257 + kc * 16 + k];
            const float4* wp = (const float4*)&wst[k * 392 + c * 28];
#pragma unroll
            for (int j = 0; j < 7; j++) {
                float4 w = wp[j];
                acc[4 * j + 0] += hv * w.x;
                acc[4 * j + 1] += hv * w.y;
                acc[4 * j + 2] += hv * w.z;
                acc[4 * j + 3] += hv * w.w;
            }
        }
    }
    int b = sids[s];
    if (b >= 0) {
        float4* dst = (float4*)&d_h2[(size_t)b * 1568 + q * 392 + c * 28];
        const float* bp = b2 + g * 1568 + q * 392 + c * 28;
#pragma unroll
        for (int j = 0; j < 7; j++) {
            float4 v;
            v.x = lrelu(acc[4 * j + 0] + bp[4 * j + 0]);
            v.y = lrelu(acc[4 * j + 1] + bp[4 * j + 1]);
            v.z = lrelu(acc[4 * j + 2] + bp[4 * j + 2]);
            v.w = lrelu(acc[4 * j + 3] + bp[4 * j + 3]);
            dst[j] = v;
        }
    }
}

// ---------------- K3: conv chain, one CTA per sample ----------------------
// smem (floats):
//   x2 : [0, 4096)        16 x 16 x 16, XOR-swizzled 16B groups per row
//   x3 : [4096, 11776)    8 x 30 x 32, XOR-swizzled 16B groups per row
//   x1 : [4096, 7552)     32 x 9 x 12 (aliases x3; dead before x3 written)
//   wb : [11776, 13896)   2048 weight stage + 72 (cw3)
// Swizzle makes multi-row float4 gathers bank-conflict-free without padding.
#define SM_X2 0
#define SM_X3 4096
#define SM_X1 4096
#define SM_WB 11776
#define SM_TOTALF 13896

// scalar (logical ch,row,col) -> physical float index
__device__ __forceinline__ int x2idx(int ch, int r, int c) {
    int sw = (r >> 1) & 3;
    return ch * 256 + r * 16 + ((((c >> 2) ^ sw)) << 2) + (c & 3);
}
__device__ __forceinline__ int x3idx(int ch, int r, int c) {
    int sw = r & 7;
    return ch * 960 + r * 32 + (((c >> 2) ^ sw) << 2) + (c & 3);
}

template<int PX>
__device__ __forceinline__ void convt1_quarter(
    const float* __restrict__ x1q, const float* __restrict__ wb,
    int my, int py, int co, float* a0, float* a1)
{
    for (int ci = 0; ci < 8; ci++) {
        const float* xc = x1q + ci * 108;           // 9*12, no swizzle
#pragma unroll
        for (int d = 0; d < 2; d++) {
            int row = my + py + 1 - d;
            float r[12];
            const float4* rp = (const float4*)(xc + row * 12);
#pragma unroll
            for (int tt = 0; tt < 3; tt++) {
                float4 vv = rp[tt];
                r[4 * tt] = vv.x; r[4 * tt + 1] = vv.y;
                r[4 * tt + 2] = vv.z; r[4 * tt + 3] = vv.w;
            }
            int jy = 1 - py + 2 * d;
#pragma unroll
            for (int e = 0; e < 2; e++) {
                int jx = 1 - PX + 2 * e;
                float2 w = *(const float2*)&wb[((ci * 4 + jy) * 4 + jx) * 16 + co];
#pragma unroll
                for (int m = 0; m < 7; m++) {
                    float xv = r[1 + PX - e + m];
                    a0[m] += w.x * xv;
                    a1[m] += w.y * xv;
                }
            }
        }
    }
}

template<int PX>
__device__ __forceinline__ void convt2_compute(
    const float* __restrict__ x2, const float* __restrict__ wb,
    int my, int py, int co, float* c0, float* c1)
{
    for (int ci = 0; ci < 16; ci++) {
        const float* xc = x2 + ci * 256;            // 16x16 swizzled
#pragma unroll
        for (int d = 0; d < 2; d++) {
            int row = my + py + 1 - d;
            int sw = (row >> 1) & 3;
            const float* rp = xc + row * 16;
            float r[16];
#pragma unroll
            for (int tt = 0; tt < 4; tt++) {
                float4 vv = *(const float4*)(rp + ((tt ^ sw) << 2));
                r[4 * tt] = vv.x; r[4 * tt + 1] = vv.y;
                r[4 * tt + 2] = vv.z; r[4 * tt + 3] = vv.w;
            }
            int jy = 1 - py + 2 * d;
#pragma unroll
            for (int e = 0; e < 2; e++) {
                int jx = 1 - PX + 2 * e;
                float2 w = *(const float2*)&wb[((ci * 4 + jy) * 4 + jx) * 8 + co];
#pragma unroll
                for (int m = 0; m < 14; m++) {
                    float xv = r[1 + PX - e + m];
                    c0[m] += w.x * xv;
                    c1[m] += w.y * xv;
                }
            }
        }
    }
}

__global__ void __launch_bounds__(256, 4) conv_kernel(
    const int* __restrict__ g_idx,
    const float* __restrict__ cw1, const float* __restrict__ cb1,
    const float* __restrict__ cw2, const float* __restrict__ cb2,
    const float* __restrict__ cw3, const float* __restrict__ cb3,
    float* __restrict__ out)
{
    extern __shared__ float sm[];
    int b = blockIdx.x;
    int g = g_idx[b];
    int tid = threadIdx.x;
    float* x1 = sm + SM_X1;
    float* x2 = sm + SM_X2;
    float* x3 = sm + SM_X3;
    float* wb = sm + SM_WB;

    int cls = tid >> 6;          // warp-uniform parity class
    int py = cls >> 1, px = cls & 1;
    int v = tid & 63;

    // ---- halo-only zeroing of x1 and x2 (through swizzle for x2) ----
    for (int i = tid; i < 32 * 38; i += 256) {       // x1: 38 halo elems/ci
        int ci = i / 38, k = i - ci * 38;
        int row, col;
        if (k < 12)      { row = 0; col = k; }
        else if (k < 24) { row = 8; col = k - 12; }
        else { int k2 = k - 24; row = 1 + (k2 >> 1); col = (k2 & 1) * 8; }
        x1[ci * 108 + row * 12 + col] = 0.f;
    }
    for (int i = tid; i < 16 * 60; i += 256) {       // x2: 60 halo elems/ci
        int ci = i / 60, k = i - ci * 60;
        int row, col;
        if (k < 16)      { row = 0;  col = k; }
        else if (k < 32) { row = 15; col = k - 16; }
        else { int k2 = k - 32; row = 1 + (k2 >> 1); col = (k2 & 1) * 15; }
        x2[x2idx(ci, row, col)] = 0.f;
    }
    __syncthreads();
    // load conv input [32,7,7] into padded x1 interior (stride 12)
    for (int i = tid; i < 1568; i += 256) {
        int ci = i / 49, r = (i / 7) % 7, cc = i % 7;
        x1[ci * 108 + (r + 1) * 12 + cc + 1] = d_h2[(size_t)b * 1568 + i];
    }

    // ---- convT1: [32,7,7] -> [16,14,14], cw1 staged in 4 quarters ----
    int my1 = v >> 3, cob1 = v & 7, co1 = cob1 * 2;   // valid when v < 56
    float a0[7], a1[7];
#pragma unroll
    for (int m = 0; m < 7; m++) { a0[m] = 0.f; a1[m] = 0.f; }

    for (int qc = 0; qc < 4; qc++) {
        __syncthreads();
        for (int i = tid; i < 2048; i += 256) {
            int ci = i >> 8, cc = (i >> 4) & 15, jy = (i >> 2) & 3, jx = i & 3;
            wb[((ci * 4 + jy) * 4 + jx) * 16 + cc] = cw1[g * 8192 + qc * 2048 + i];
        }
        __syncthreads();
        if (v < 56) {
            const float* x1q = x1 + qc * 8 * 108;
            if (px == 0) convt1_quarter<0>(x1q, wb, my1, py, co1, a0, a1);
            else         convt1_quarter<1>(x1q, wb, my1, py, co1, a0, a1);
        }
    }
    if (v < 56) {
        float bb0 = cb1[g * 16 + co1], bb1 = cb1[g * 16 + co1 + 1];
        int oy = 2 * my1 + py;
#pragma unroll
        for (int m = 0; m < 7; m++) {
            int ox = 2 * m + px;
            x2[x2idx(co1,     oy + 1, ox + 1)] = lrelu(a0[m] + bb0);
            x2[x2idx(co1 + 1, oy + 1, ox + 1)] = lrelu(a1[m] + bb1);
        }
    }
    __syncthreads();     // convT1 done; x1 dead

    // halo-zero x3 (through swizzle), stage cw2 + cw3
    for (int i = tid; i < 8 * 116; i += 256) {
        int ci = i / 116, k = i - ci * 116;
        int row, col;
        if (k < 30)      { row = 0;  col = k; }
        else if (k < 60) { row = 29; col = k - 30; }
        else { int k2 = k - 60; row = 1 + (k2 >> 1); col = (k2 & 1) * 29; }
        x3[x3idx(ci, row, col)] = 0.f;
    }
    for (int i = tid; i < 2048; i += 256) {
        int ci = i >> 7, cc = (i >> 4) & 7, jy = (i >> 2) & 3, jx = i & 3;
        wb[((ci * 4 + jy) * 4 + jx) * 8 + cc] = cw2[g * 2048 + i];
    }
    if (tid < 72) wb[2048 + tid] = cw3[g * 72 + tid];
    __syncthreads();

    // ---- convT2: [16,14,14] -> [8,28,28] ----
    if (v < 56) {
        int my = v >> 2, co = (v & 3) * 2;
        float c0[14], c1[14];
#pragma unroll
        for (int m = 0; m < 14; m++) { c0[m] = 0.f; c1[m] = 0.f; }
        if (px == 0) convt2_compute<0>(x2, wb, my, py, co, c0, c1);
        else         convt2_compute<1>(x2, wb, my, py, co, c0, c1);
        float bb0 = cb2[g * 8 + co], bb1 = cb2[g * 8 + co + 1];
        int oy = 2 * my + py;
#pragma unroll
        for (int m = 0; m < 14; m++) {
            int ox = 2 * m + px;
            x3[x3idx(co,     oy + 1, ox + 1)] = lrelu(c0[m] + bb0);
            x3[x3idx(co + 1, oy + 1, ox + 1)] = lrelu(c1[m] + bb1);
        }
    }
    __syncthreads();

    // ---- convT3 (stride1 k3 p1): [8,28,28] -> [1,28,28], tanh ----
    // 196 threads: tid = oy*7 + seg, seg = 4-wide output segment.
    if (tid < 196) {
        int oy = tid / 7, s = tid - oy * 7;      // s in 0..6
        float bb = cb3[g];
        float acc[4];
#pragma unroll
        for (int u = 0; u < 4; u++) acc[u] = bb;
        const float* w3 = wb + 2048;
        for (int ci = 0; ci < 8; ci++) {
#pragma unroll
            for (int jy = 0; jy < 3; jy++) {
                int row = oy + 2 - jy;
                int sw = row & 7;
                const float* base = x3 + (ci * 30 + row) * 32;
                float r[8];
                float4 v0 = *(const float4*)(base + ((s ^ sw) << 2));
                float4 v1 = *(const float4*)(base + (((s + 1) ^ sw) << 2));
                r[0] = v0.x; r[1] = v0.y; r[2] = v0.z; r[3] = v0.w;
                r[4] = v1.x; r[5] = v1.y; r[6] = v1.z; r[7] = v1.w;
                const float* wr = w3 + ci * 9 + jy * 3;
#pragma unroll
                for (int jx = 0; jx < 3; jx++) {
                    float wv = wr[jx];
#pragma unroll
                    for (int u = 0; u < 4; u++)
                        acc[u] += wv * r[u + 2 - jx];
                }
            }
        }
        float4 o;
        o.x = tanhf(acc[0]); o.y = tanhf(acc[1]);
        o.z = tanhf(acc[2]); o.w = tanhf(acc[3]);
        *(float4*)(out + (size_t)b * 784 + oy * 28 + s * 4) = o;
    }
}

// ---------------- launch ----------------
extern "C" void kernel_launch(void* const* d_in, const int* in_sizes, int n_in,
                              void* d_out, int out_size)
{
    (void)in_sizes; (void)n_in; (void)out_size;
    const float* z   = (const float*)d_in[0];
    const int*   gi  = (const int*)d_in[1];
    const float* W1  = (const float*)d_in[2];
    const float* b1  = (const float*)d_in[3];
    const float* W2  = (const float*)d_in[4];
    const float* b2  = (const float*)d_in[5];
    const float* cw1 = (const float*)d_in[6];
    const float* cb1 = (const float*)d_in[7];
    const float* cw2 = (const float*)d_in[8];
    const float* cb2 = (const float*)d_in[9];
    const float* cw3 = (const float*)d_in[10];
    const float* cb3 = (const float*)d_in[11];
    float* out = (float*)d_out;

    group_kernel<<<1, 256>>>(gi);
    fc1_kernel<<<NTILES, 256>>>(z, W1, b1);
    fc2_kernel<<<dim3(NTILES, 4), 224>>>(W2, b2);
    cudaFuncSetAttribute(conv_kernel,
                         cudaFuncAttributeMaxDynamicSharedMemorySize,
                         SM_TOTALF * 4);
    conv_kernel<<<BATCH, 256, SM_TOTALF * 4>>>(gi, cw1, cb1, cw2, cb2,
                                               cw3, cb3, out);
}

// round 6
// speedup vs baseline: 2.1535x; 1.1337x over previous
#include <cuda_runtime.h>
#include <math.h>

#define BATCH 2048
#define NZ 128
#define NGEN 8
#define TS 16
#define NTILES 136   // ceil((2048 + 8*15)/16)

typedef unsigned long long u64;

// packed f32x2 helpers (Blackwell FFMA2 path)
__device__ __forceinline__ u64 pk(float lo, float hi) {
    u64 r; asm("mov.b64 %0,{%1,%2};" : "=l"(r) : "f"(lo), "f"(hi)); return r;
}
__device__ __forceinline__ void upk(u64 v, float& lo, float& hi) {
    asm("mov.b64 {%0,%1},%2;" : "=f"(lo), "=f"(hi) : "l"(v));
}
__device__ __forceinline__ void fma2(u64& d, u64 a, u64 b) {
    asm("fma.rn.f32x2 %0,%1,%2,%3;" : "=l"(d) : "l"(a), "l"(b), "l"(d));
}

// ---------------- device scratch (no allocations allowed) ----------------
__device__ float d_h1[BATCH * 256];     // FC1 output
__device__ float d_h2[BATCH * 1568];    // FC2 output (conv input)
__device__ int   d_perm[NTILES * TS];   // samples grouped by generator, -1 padded
__device__ int   d_tileg[NTILES];       // generator per tile, -1 = empty

__device__ __forceinline__ float lrelu(float x) { return x > 0.f ? x : 0.2f * x; }

// ---------------- K0: group samples by generator into padded 16-tiles ----
__global__ void group_kernel(const int* __restrict__ g_idx) {
    __shared__ int cnt[NGEN], base[NGEN], cur[NGEN];
    int tid = threadIdx.x;
    if (tid < NGEN) { cnt[tid] = 0; cur[tid] = 0; }
    __syncthreads();
    for (int b = tid; b < BATCH; b += blockDim.x)
        atomicAdd(&cnt[g_idx[b]], 1);
    for (int i = tid; i < NTILES * TS; i += blockDim.x)
        d_perm[i] = -1;
    __syncthreads();
    if (tid == 0) {
        int off = 0;
        for (int g = 0; g < NGEN; g++) {
            base[g] = off;
            off += ((cnt[g] + TS - 1) / TS) * TS;
        }
    }
    __syncthreads();
    for (int b = tid; b < BATCH; b += blockDim.x) {
        int g = g_idx[b];
        int p = atomicAdd(&cur[g], 1);
        d_perm[base[g] + p] = b;
    }
    for (int t = tid; t < NTILES; t += blockDim.x) {
        int start = t * TS, gg = -1;
        for (int g = 0; g < NGEN; g++) {
            int padded = ((cnt[g] + TS - 1) / TS) * TS;
            if (start >= base[g] && start < base[g] + padded) gg = g;
        }
        d_tileg[t] = gg;
    }
}

// ---------------- K1: FC1  h1 = lrelu(z @ W1[g] + b1[g]) ------------------
__global__ void __launch_bounds__(256) fc1_kernel(
    const float* __restrict__ z, const float* __restrict__ W1,
    const float* __restrict__ b1)
{
    int t = blockIdx.x;
    int g = d_tileg[t];
    if (g < 0) return;
    __shared__ int sids[TS];
    __shared__ float zsm[TS * 130];
    __shared__ __align__(16) float wst[16 * 256];
    int tid = threadIdx.x;
    if (tid < TS) sids[tid] = d_perm[t * TS + tid];
    __syncthreads();
    for (int i = tid; i < TS * NZ; i += 256) {
        int s = i >> 7, k = i & 127;
        int b = sids[s];
        zsm[s * 130 + k] = (b >= 0) ? z[b * NZ + k] : 0.f;
    }
    int s = tid & 15, c = tid >> 4;
    float acc[16];
#pragma unroll
    for (int j = 0; j < 16; j++) acc[j] = 0.f;
    const float* Wg = W1 + (size_t)g * NZ * 256;
    for (int kc = 0; kc < 8; kc++) {
        __syncthreads();
#pragma unroll
        for (int j = 0; j < 16; j++) {
            int idx = tid + 256 * j;
            wst[idx] = Wg[(kc * 16 + (idx >> 8)) * 256 + (idx & 255)];
        }
        __syncthreads();
#pragma unroll
        for (int k = 0; k < 16; k++) {
            float zv = zsm[s * 130 + kc * 16 + k];
            const float4* wp = (const float4*)&wst[k * 256 + c * 16];
#pragma unroll
            for (int j = 0; j < 4; j++) {
                float4 w = wp[j];
                acc[4 * j + 0] += zv * w.x;
                acc[4 * j + 1] += zv * w.y;
                acc[4 * j + 2] += zv * w.z;
                acc[4 * j + 3] += zv * w.w;
            }
        }
    }
    int b = sids[s];
    if (b >= 0) {
#pragma unroll
        for (int j = 0; j < 16; j++)
            acc[j] = lrelu(acc[j] + b1[g * 256 + c * 16 + j]);
        float4* dst = (float4*)&d_h1[b * 256 + c * 16];
#pragma unroll
        for (int j = 0; j < 4; j++)
            dst[j] = make_float4(acc[4 * j], acc[4 * j + 1], acc[4 * j + 2], acc[4 * j + 3]);
    }
}

// ---------------- K2: FC2  h2 = lrelu(h1 @ W2[g] + b2[g]) -----------------
// 224 threads: s = tid&7 (handles samples s and s+8), c = tid>>3 (0..27),
// 14 outputs per sample. Packed FFMA2 across output pairs; weight pairs are
// native LDS.64; hv duplicated once per sample per k.
__global__ void __launch_bounds__(224) fc2_kernel(
    const float* __restrict__ W2, const float* __restrict__ b2)
{
    int t = blockIdx.x, q = blockIdx.y;   // q in 0..3, 392 outputs per q
    int g = d_tileg[t];
    if (g < 0) return;
    __shared__ int sids[TS];
    __shared__ float h1sm[TS * 257];
    __shared__ __align__(16) float wst[16 * 392];
    int tid = threadIdx.x;
    if (tid < TS) sids[tid] = d_perm[t * TS + tid];
    __syncthreads();
    for (int i = tid; i < TS * 256; i += 224) {
        int s = i >> 8, k = i & 255;
        int b = sids[s];
        h1sm[s * 257 + k] = (b >= 0) ? d_h1[b * 256 + k] : 0.f;
    }
    int s = tid & 7, c = tid >> 3;
    u64 A0[7], A1[7];
#pragma unroll
    for (int j = 0; j < 7; j++) { A0[j] = 0ULL; A1[j] = 0ULL; }
    const float* Wg = W2 + (size_t)g * 256 * 1568 + q * 392;
    for (int kc = 0; kc < 16; kc++) {
        __syncthreads();
#pragma unroll
        for (int j = 0; j < 28; j++) {
            int i = tid + 224 * j;
            int row = i / 392, col = i - row * 392;
            wst[i] = Wg[(kc * 16 + row) * 1568 + col];
        }
        __syncthreads();
#pragma unroll
        for (int k = 0; k < 16; k++) {
            float hv0 = h1sm[s * 257 + kc * 16 + k];
            float hv1 = h1sm[(s + 8) * 257 + kc * 16 + k];
            u64 H0 = pk(hv0, hv0), H1 = pk(hv1, hv1);
            const u64* wp = (const u64*)&wst[k * 392 + c * 14];
#pragma unroll
            for (int j = 0; j < 7; j++) {
                u64 w = wp[j];
                fma2(A0[j], w, H0);
                fma2(A1[j], w, H1);
            }
        }
    }
    int ob = q * 392 + c * 14;
    const float* bp = b2 + g * 1568 + ob;
    int b0 = sids[s], b1v = sids[s + 8];
    if (b0 >= 0) {
        float2* dst = (float2*)&d_h2[(size_t)b0 * 1568 + ob];
#pragma unroll
        for (int j = 0; j < 7; j++) {
            float lo, hi; upk(A0[j], lo, hi);
            float2 v;
            v.x = lrelu(lo + bp[2 * j]);
            v.y = lrelu(hi + bp[2 * j + 1]);
            dst[j] = v;
        }
    }
    if (b1v >= 0) {
        float2* dst = (float2*)&d_h2[(size_t)b1v * 1568 + ob];
#pragma unroll
        for (int j = 0; j < 7; j++) {
            float lo, hi; upk(A1[j], lo, hi);
            float2 v;
            v.x = lrelu(lo + bp[2 * j]);
            v.y = lrelu(hi + bp[2 * j + 1]);
            dst[j] = v;
        }
    }
}

// ---------------- K3: conv chain, one CTA per sample ----------------------
// smem (floats):
//   x2 : [0, 4096)        16 x 16 x 16, XOR-swizzled 16B groups per row
//   x3 : [4096, 11776)    8 x 30 x 32, XOR-swizzled 16B groups per row
//   x1 : [4096, 7552)     32 x 9 x 12 (aliases x3; dead before x3 written)
//   wb : [11776, 13896)   2048 weight stage + 72 (cw3)
#define SM_X2 0
#define SM_X3 4096
#define SM_X1 4096
#define SM_WB 11776
#define SM_TOTALF 13896

__device__ __forceinline__ int x2idx(int ch, int r, int c) {
    int sw = (r >> 1) & 3;
    return ch * 256 + r * 16 + ((((c >> 2) ^ sw)) << 2) + (c & 3);
}
__device__ __forceinline__ int x3idx(int ch, int r, int c) {
    int sw = r & 7;
    return ch * 960 + r * 32 + (((c >> 2) ^ sw) << 2) + (c & 3);
}

// A[m] = packed (c_co[m], c_co+1[m]); acc via FFMA2, weight pair native LDS.64.
template<int PX>
__device__ __forceinline__ void convt1_quarter(
    const float* __restrict__ x1q, const float* __restrict__ wb,
    int my, int py, int co, u64* A)
{
#pragma unroll
    for (int ci = 0; ci < 8; ci++) {
        const float* xc = x1q + ci * 108;           // 9*12, no swizzle
#pragma unroll
        for (int d = 0; d < 2; d++) {
            int row = my + py + 1 - d;
            float r[12];
            const float4* rp = (const float4*)(xc + row * 12);
#pragma unroll
            for (int tt = 0; tt < 3; tt++) {
                float4 vv = rp[tt];
                r[4 * tt] = vv.x; r[4 * tt + 1] = vv.y;
                r[4 * tt + 2] = vv.z; r[4 * tt + 3] = vv.w;
            }
            int jy = 1 - py + 2 * d;
            u64 w0 = *(const u64*)&wb[((ci * 4 + jy) * 4 + (1 - PX)) * 16 + co];
            u64 w1 = *(const u64*)&wb[((ci * 4 + jy) * 4 + (3 - PX)) * 16 + co];
            // e=0 (w0): x = r[1+PX+m]; e=1 (w1): x = r[PX+m]
            u64 xa = pk(r[PX], r[PX]);
#pragma unroll
            for (int m = 0; m < 7; m++) {
                u64 xb = pk(r[PX + 1 + m], r[PX + 1 + m]);
                fma2(A[m], w1, xa);
                fma2(A[m], w0, xb);
                xa = xb;
            }
        }
    }
}

template<int PX>
__device__ __forceinline__ void convt2_compute(
    const float* __restrict__ x2, const float* __restrict__ wb,
    int my, int py, int co, u64* A)
{
#pragma unroll 4
    for (int ci = 0; ci < 16; ci++) {
        const float* xc = x2 + ci * 256;            // 16x16 swizzled
#pragma unroll
        for (int d = 0; d < 2; d++) {
            int row = my + py + 1 - d;
            int sw = (row >> 1) & 3;
            const float* rp = xc + row * 16;
            float r[16];
#pragma unroll
            for (int tt = 0; tt < 4; tt++) {
                float4 vv = *(const float4*)(rp + ((tt ^ sw) << 2));
                r[4 * tt] = vv.x; r[4 * tt + 1] = vv.y;
                r[4 * tt + 2] = vv.z; r[4 * tt + 3] = vv.w;
            }
            int jy = 1 - py + 2 * d;
            u64 w0 = *(const u64*)&wb[((ci * 4 + jy) * 4 + (1 - PX)) * 8 + co];
            u64 w1 = *(const u64*)&wb[((ci * 4 + jy) * 4 + (3 - PX)) * 8 + co];
            u64 xa = pk(r[PX], r[PX]);
#pragma unroll
            for (int m = 0; m < 14; m++) {
                u64 xb = pk(r[PX + 1 + m], r[PX + 1 + m]);
                fma2(A[m], w1, xa);
                fma2(A[m], w0, xb);
                xa = xb;
            }
        }
    }
}

__global__ void __launch_bounds__(256, 4) conv_kernel(
    const int* __restrict__ g_idx,
    const float* __restrict__ cw1, const float* __restrict__ cb1,
    const float* __restrict__ cw2, const float* __restrict__ cb2,
    const float* __restrict__ cw3, const float* __restrict__ cb3,
    float* __restrict__ out)
{
    extern __shared__ float sm[];
    int b = blockIdx.x;
    int g = g_idx[b];
    int tid = threadIdx.x;
    float* x1 = sm + SM_X1;
    float* x2 = sm + SM_X2;
    float* x3 = sm + SM_X3;
    float* wb = sm + SM_WB;

    int cls = tid >> 6;          // warp-uniform parity class
    int py = cls >> 1, px = cls & 1;
    int v = tid & 63;

    // ---- halo-only zeroing of x1 and x2 (through swizzle for x2) ----
    for (int i = tid; i < 32 * 38; i += 256) {       // x1: 38 halo elems/ci
        int ci = i / 38, k = i - ci * 38;
        int row, col;
        if (k < 12)      { row = 0; col = k; }
        else if (k < 24) { row = 8; col = k - 12; }
        else { int k2 = k - 24; row = 1 + (k2 >> 1); col = (k2 & 1) * 8; }
        x1[ci * 108 + row * 12 + col] = 0.f;
    }
    for (int i = tid; i < 16 * 60; i += 256) {       // x2: 60 halo elems/ci
        int ci = i / 60, k = i - ci * 60;
        int row, col;
        if (k < 16)      { row = 0;  col = k; }
        else if (k < 32) { row = 15; col = k - 16; }
        else { int k2 = k - 32; row = 1 + (k2 >> 1); col = (k2 & 1) * 15; }
        x2[x2idx(ci, row, col)] = 0.f;
    }
    __syncthreads();
    // load conv input [32,7,7] into padded x1 interior (stride 12)
    for (int i = tid; i < 1568; i += 256) {
        int ci = i / 49, r = (i / 7) % 7, cc = i % 7;
        x1[ci * 108 + (r + 1) * 12 + cc + 1] = d_h2[(size_t)b * 1568 + i];
    }

    // ---- convT1: [32,7,7] -> [16,14,14], cw1 staged in 4 quarters ----
    int my1 = v >> 3, cob1 = v & 7, co1 = cob1 * 2;   // valid when v < 56
    u64 A1c[7];
#pragma unroll
    for (int m = 0; m < 7; m++) A1c[m] = 0ULL;

    for (int qc = 0; qc < 4; qc++) {
        __syncthreads();
        for (int i = tid; i < 2048; i += 256) {
            int ci = i >> 8, cc = (i >> 4) & 15, jy = (i >> 2) & 3, jx = i & 3;
            wb[((ci * 4 + jy) * 4 + jx) * 16 + cc] = cw1[g * 8192 + qc * 2048 + i];
        }
        __syncthreads();
        if (v < 56) {
            const float* x1q = x1 + qc * 8 * 108;
            if (px == 0) convt1_quarter<0>(x1q, wb, my1, py, co1, A1c);
            else         convt1_quarter<1>(x1q, wb, my1, py, co1, A1c);
        }
    }
    if (v < 56) {
        float bb0 = cb1[g * 16 + co1], bb1 = cb1[g * 16 + co1 + 1];
        int oy = 2 * my1 + py;
#pragma unroll
        for (int m = 0; m < 7; m++) {
            int ox = 2 * m + px;
            float lo, hi; upk(A1c[m], lo, hi);
            x2[x2idx(co1,     oy + 1, ox + 1)] = lrelu(lo + bb0);
            x2[x2idx(co1 + 1, oy + 1, ox + 1)] = lrelu(hi + bb1);
        }
    }
    __syncthreads();     // convT1 done; x1 dead

    // halo-zero x3 (through swizzle), stage cw2 + cw3
    for (int i = tid; i < 8 * 116; i += 256) {
        int ci = i / 116, k = i - ci * 116;
        int row, col;
        if (k < 30)      { row = 0;  col = k; }
        else if (k < 60) { row = 29; col = k - 30; }
        else { int k2 = k - 60; row = 1 + (k2 >> 1); col = (k2 & 1) * 29; }
        x3[x3idx(ci, row, col)] = 0.f;
    }
    for (int i = tid; i < 2048; i += 256) {
        int ci = i >> 7, cc = (i >> 4) & 7, jy = (i >> 2) & 3, jx = i & 3;
        wb[((ci * 4 + jy) * 4 + jx) * 8 + cc] = cw2[g * 2048 + i];
    }
    if (tid < 72) wb[2048 + tid] = cw3[g * 72 + tid];
    __syncthreads();

    // ---- convT2: [16,14,14] -> [8,28,28] ----
    if (v < 56) {
        int my = v >> 2, co = (v & 3) * 2;
        u64 A2c[14];
#pragma unroll
        for (int m = 0; m < 14; m++) A2c[m] = 0ULL;
        if (px == 0) convt2_compute<0>(x2, wb, my, py, co, A2c);
        else         convt2_compute<1>(x2, wb, my, py, co, A2c);
        float bb0 = cb2[g * 8 + co], bb1 = cb2[g * 8 + co + 1];
        int oy = 2 * my + py;
#pragma unroll
        for (int m = 0; m < 14; m++) {
            int ox = 2 * m + px;
            float lo, hi; upk(A2c[m], lo, hi);
            x3[x3idx(co,     oy + 1, ox + 1)] = lrelu(lo + bb0);
            x3[x3idx(co + 1, oy + 1, ox + 1)] = lrelu(hi + bb1);
        }
    }
    __syncthreads();

    // ---- convT3 (stride1 k3 p1): [8,28,28] -> [1,28,28], tanh ----
    if (tid < 196) {
        int oy = tid / 7, s = tid - oy * 7;      // s in 0..6
        float bb = cb3[g];
        float acc[4];
#pragma unroll
        for (int u = 0; u < 4; u++) acc[u] = bb;
        const float* w3 = wb + 2048;
        for (int ci = 0; ci < 8; ci++) {
#pragma unroll
            for (int jy = 0; jy < 3; jy++) {
                int row = oy + 2 - jy;
                int sw = row & 7;
                const float* base = x3 + (ci * 30 + row) * 32;
                float r[8];
                float4 v0 = *(const float4*)(base + ((s ^ sw) << 2));
                float4 v1 = *(const float4*)(base + (((s + 1) ^ sw) << 2));
                r[0] = v0.x; r[1] = v0.y; r[2] = v0.z; r[3] = v0.w;
                r[4] = v1.x; r[5] = v1.y; r[6] = v1.z; r[7] = v1.w;
                const float* wr = w3 + ci * 9 + jy * 3;
#pragma unroll
                for (int jx = 0; jx < 3; jx++) {
                    float wv = wr[jx];
#pragma unroll
                    for (int u = 0; u < 4; u++)
                        acc[u] += wv * r[u + 2 - jx];
                }
            }
        }
        float4 o;
        o.x = tanhf(acc[0]); o.y = tanhf(acc[1]);
        o.z = tanhf(acc[2]); o.w = tanhf(acc[3]);
        *(float4*)(out + (size_t)b * 784 + oy * 28 + s * 4) = o;
    }
}

// ---------------- launch ----------------
extern "C" void kernel_launch(void* const* d_in, const int* in_sizes, int n_in,
                              void* d_out, int out_size)
{
    (void)in_sizes; (void)n_in; (void)out_size;
    const float* z   = (const float*)d_in[0];
    const int*   gi  = (const int*)d_in[1];
    const float* W1  = (const float*)d_in[2];
    const float* b1  = (const float*)d_in[3];
    const float* W2  = (const float*)d_in[4];
    const float* b2  = (const float*)d_in[5];
    const float* cw1 = (const float*)d_in[6];
    const float* cb1 = (const float*)d_in[7];
    const float* cw2 = (const float*)d_in[8];
    const float* cb2 = (const float*)d_in[9];
    const float* cw3 = (const float*)d_in[10];
    const float* cb3 = (const float*)d_in[11];
    float* out = (float*)d_out;

    group_kernel<<<1, 256>>>(gi);
    fc1_kernel<<<NTILES, 256>>>(z, W1, b1);
    fc2_kernel<<<dim3(NTILES, 4), 224>>>(W2, b2);
    cudaFuncSetAttribute(conv_kernel,
                         cudaFuncAttributeMaxDynamicSharedMemorySize,
                         SM_TOTALF * 4);
    conv_kernel<<<BATCH, 256, SM_TOTALF * 4>>>(gi, cw1, cb1, cw2, cb2,
                                               cw3, cb3, out);
}

// round 7
// speedup vs baseline: 2.3910x; 1.1103x over previous
#include <cuda_runtime.h>
#include <math.h>

#define BATCH 2048
#define NZ 128
#define NGEN 8
#define TS 16
#define NTILES 136   // ceil((2048 + 8*15)/16)

typedef unsigned long long u64;

// packed f32x2 helpers (Blackwell FFMA2 path)
__device__ __forceinline__ u64 pk(float lo, float hi) {
    u64 r; asm("mov.b64 %0,{%1,%2};" : "=l"(r) : "f"(lo), "f"(hi)); return r;
}
__device__ __forceinline__ void upk(u64 v, float& lo, float& hi) {
    asm("mov.b64 {%0,%1},%2;" : "=f"(lo), "=f"(hi) : "l"(v));
}
__device__ __forceinline__ void fma2(u64& d, u64 a, u64 b) {
    asm("fma.rn.f32x2 %0,%1,%2,%3;" : "=l"(d) : "l"(a), "l"(b), "l"(d));
}

// ---------------- device scratch (no allocations allowed) ----------------
__device__ float d_h1[BATCH * 256];     // FC1 output
__device__ float d_h2[BATCH * 1568];    // FC2 output (conv input)
__device__ int   d_perm[NTILES * TS];   // samples grouped by generator, -1 padded
__device__ int   d_tileg[NTILES];       // generator per tile, -1 = empty

__device__ __forceinline__ float lrelu(float x) { return x > 0.f ? x : 0.2f * x; }

// ---------------- K0: group samples by generator into padded 16-tiles ----
__global__ void group_kernel(const int* __restrict__ g_idx) {
    __shared__ int cnt[NGEN], base[NGEN], cur[NGEN];
    int tid = threadIdx.x;
    if (tid < NGEN) { cnt[tid] = 0; cur[tid] = 0; }
    __syncthreads();
    for (int b = tid; b < BATCH; b += blockDim.x)
        atomicAdd(&cnt[g_idx[b]], 1);
    for (int i = tid; i < NTILES * TS; i += blockDim.x)
        d_perm[i] = -1;
    __syncthreads();
    if (tid == 0) {
        int off = 0;
        for (int g = 0; g < NGEN; g++) {
            base[g] = off;
            off += ((cnt[g] + TS - 1) / TS) * TS;
        }
    }
    __syncthreads();
    for (int b = tid; b < BATCH; b += blockDim.x) {
        int g = g_idx[b];
        int p = atomicAdd(&cur[g], 1);
        d_perm[base[g] + p] = b;
    }
    for (int t = tid; t < NTILES; t += blockDim.x) {
        int start = t * TS, gg = -1;
        for (int g = 0; g < NGEN; g++) {
            int padded = ((cnt[g] + TS - 1) / TS) * TS;
            if (start >= base[g] && start < base[g] + padded) gg = g;
        }
        d_tileg[t] = gg;
    }
}

// ---------------- K1: FC1  h1 = lrelu(z @ W1[g] + b1[g]) ------------------
// 256 thr: s = tid&7 (samples s, s+8), c = tid>>3 (0..31, 8 outputs each).
__global__ void __launch_bounds__(256) fc1_kernel(
    const float* __restrict__ z, const float* __restrict__ W1,
    const float* __restrict__ b1)
{
    int t = blockIdx.x;
    int g = d_tileg[t];
    if (g < 0) return;
    __shared__ int sids[TS];
    __shared__ __align__(16) float zsm[TS * 132];
    __shared__ __align__(16) float wst[16 * 256];
    int tid = threadIdx.x;
    if (tid < TS) sids[tid] = d_perm[t * TS + tid];
    __syncthreads();
    // z staging, float4
    for (int i4 = tid; i4 < TS * 32; i4 += 256) {
        int s = i4 >> 5, k4 = i4 & 31;
        int b = sids[s];
        float4 vv = (b >= 0) ? ((const float4*)z)[b * 32 + k4]
                             : make_float4(0.f, 0.f, 0.f, 0.f);
        ((float4*)zsm)[s * 33 + k4] = vv;
    }
    int s = tid & 7, c = tid >> 3;
    u64 A0[4], A1[4];
#pragma unroll
    for (int j = 0; j < 4; j++) { A0[j] = 0ULL; A1[j] = 0ULL; }
    const float* Wg = W1 + (size_t)g * NZ * 256;
    for (int kc = 0; kc < 8; kc++) {
        __syncthreads();
#pragma unroll
        for (int j = 0; j < 4; j++) {
            int i4 = tid + 256 * j;          // 1024 float4 per stage
            ((float4*)wst)[i4] = ((const float4*)Wg)[kc * 1024 + i4];
        }
        __syncthreads();
#pragma unroll
        for (int k = 0; k < 16; k++) {
            float hv0 = zsm[s * 132 + kc * 16 + k];
            float hv1 = zsm[(s + 8) * 132 + kc * 16 + k];
            u64 H0 = pk(hv0, hv0), H1 = pk(hv1, hv1);
            const u64* wp = (const u64*)&wst[k * 256 + c * 8];
#pragma unroll
            for (int j = 0; j < 4; j++) {
                u64 w = wp[j];
                fma2(A0[j], w, H0);
                fma2(A1[j], w, H1);
            }
        }
    }
    const float* bp = b1 + g * 256 + c * 8;
    int b0 = sids[s], b1v = sids[s + 8];
    if (b0 >= 0) {
        float2* dst = (float2*)&d_h1[b0 * 256 + c * 8];
#pragma unroll
        for (int j = 0; j < 4; j++) {
            float lo, hi; upk(A0[j], lo, hi);
            float2 vv;
            vv.x = lrelu(lo + bp[2 * j]);
            vv.y = lrelu(hi + bp[2 * j + 1]);
            dst[j] = vv;
        }
    }
    if (b1v >= 0) {
        float2* dst = (float2*)&d_h1[b1v * 256 + c * 8];
#pragma unroll
        for (int j = 0; j < 4; j++) {
            float lo, hi; upk(A1[j], lo, hi);
            float2 vv;
            vv.x = lrelu(lo + bp[2 * j]);
            vv.y = lrelu(hi + bp[2 * j + 1]);
            dst[j] = vv;
        }
    }
}

// ---------------- K2: FC2  h2 = lrelu(h1 @ W2[g] + b2[g]) -----------------
// 224 thr: s = tid&7 (samples s, s+8), c = tid>>3 (0..27, 14 outputs each).
__global__ void __launch_bounds__(224) fc2_kernel(
    const float* __restrict__ W2, const float* __restrict__ b2)
{
    int t = blockIdx.x, q = blockIdx.y;   // q in 0..3, 392 outputs per q
    int g = d_tileg[t];
    if (g < 0) return;
    __shared__ int sids[TS];
    __shared__ __align__(16) float h1sm[TS * 260];
    __shared__ __align__(16) float wst[16 * 392];
    int tid = threadIdx.x;
    if (tid < TS) sids[tid] = d_perm[t * TS + tid];
    __syncthreads();
    // h1 staging, float4 (1024 float4)
    for (int i4 = tid; i4 < TS * 64; i4 += 224) {
        int s = i4 >> 6, k4 = i4 & 63;
        int b = sids[s];
        float4 vv = (b >= 0) ? ((const float4*)d_h1)[b * 64 + k4]
                             : make_float4(0.f, 0.f, 0.f, 0.f);
        ((float4*)h1sm)[s * 65 + k4] = vv;
    }
    int s = tid & 7, c = tid >> 3;
    u64 A0[7], A1[7];
#pragma unroll
    for (int j = 0; j < 7; j++) { A0[j] = 0ULL; A1[j] = 0ULL; }
    const float* Wg = W2 + (size_t)g * 256 * 1568 + q * 392;
    for (int kc = 0; kc < 16; kc++) {
        __syncthreads();
#pragma unroll
        for (int j = 0; j < 7; j++) {        // 1568 float4 per stage
            int i4 = tid + 224 * j;
            int row = i4 / 98, c4 = i4 - row * 98;
            ((float4*)wst)[row * 98 + c4] =
                ((const float4*)Wg)[(kc * 16 + row) * 392 + c4];
        }
        __syncthreads();
#pragma unroll
        for (int k = 0; k < 16; k++) {
            float hv0 = h1sm[s * 260 + kc * 16 + k];
            float hv1 = h1sm[(s + 8) * 260 + kc * 16 + k];
            u64 H0 = pk(hv0, hv0), H1 = pk(hv1, hv1);
            const u64* wp = (const u64*)&wst[k * 392 + c * 14];
#pragma unroll
            for (int j = 0; j < 7; j++) {
                u64 w = wp[j];
                fma2(A0[j], w, H0);
                fma2(A1[j], w, H1);
            }
        }
    }
    int ob = q * 392 + c * 14;
    const float* bp = b2 + g * 1568 + ob;
    int b0 = sids[s], b1v = sids[s + 8];
    if (b0 >= 0) {
        float2* dst = (float2*)&d_h2[(size_t)b0 * 1568 + ob];
#pragma unroll
        for (int j = 0; j < 7; j++) {
            float lo, hi; upk(A0[j], lo, hi);
            float2 vv;
            vv.x = lrelu(lo + bp[2 * j]);
            vv.y = lrelu(hi + bp[2 * j + 1]);
            dst[j] = vv;
        }
    }
    if (b1v >= 0) {
        float2* dst = (float2*)&d_h2[(size_t)b1v * 1568 + ob];
#pragma unroll
        for (int j = 0; j < 7; j++) {
            float lo, hi; upk(A1[j], lo, hi);
            float2 vv;
            vv.x = lrelu(lo + bp[2 * j]);
            vv.y = lrelu(hi + bp[2 * j + 1]);
            dst[j] = vv;
        }
    }
}

// ---------------- K3: conv chain, 2 samples per CTA (512 threads) ---------
// Both samples come from the same generator tile (via d_perm), sharing the
// staged weights. smem (floats):
//   per half h: [h*11776 .. ) : x2 (4096) | x3 (7680); x1 (3456) aliases x3
//   wb : [23552, 27776)  4096 cw1-half stage, later cw2(2048)+cw3(72)
#define SM_HALF 11776
#define SM_WB 23552
#define SM_TOTALF 27776

__device__ __forceinline__ int x2idx(int ch, int r, int c) {
    int sw = (r >> 1) & 3;
    return ch * 256 + r * 16 + ((((c >> 2) ^ sw)) << 2) + (c & 3);
}
__device__ __forceinline__ int x3idx(int ch, int r, int c) {
    int sw = r & 7;
    return ch * 960 + r * 32 + (((c >> 2) ^ sw) << 2) + (c & 3);
}

// A[m] = packed (c_co[m], c_co+1[m]); FFMA2, weight pair native LDS.64.
template<int PX>
__device__ __forceinline__ void convt1_half(
    const float* __restrict__ x1q, const float* __restrict__ wb,
    int my, int py, int co, u64* A)
{
#pragma unroll
    for (int ci = 0; ci < 16; ci++) {
        const float* xc = x1q + ci * 108;           // 9*12, no swizzle
#pragma unroll
        for (int d = 0; d < 2; d++) {
            int row = my + py + 1 - d;
            float r[12];
            const float4* rp = (const float4*)(xc + row * 12);
#pragma unroll
            for (int tt = 0; tt < 3; tt++) {
                float4 vv = rp[tt];
                r[4 * tt] = vv.x; r[4 * tt + 1] = vv.y;
                r[4 * tt + 2] = vv.z; r[4 * tt + 3] = vv.w;
            }
            int jy = 1 - py + 2 * d;
            u64 w0 = *(const u64*)&wb[((ci * 4 + jy) * 4 + (1 - PX)) * 16 + co];
            u64 w1 = *(const u64*)&wb[((ci * 4 + jy) * 4 + (3 - PX)) * 16 + co];
            u64 xa = pk(r[PX], r[PX]);
#pragma unroll
            for (int m = 0; m < 7; m++) {
                u64 xb = pk(r[PX + 1 + m], r[PX + 1 + m]);
                fma2(A[m], w1, xa);
                fma2(A[m], w0, xb);
                xa = xb;
            }
        }
    }
}

template<int PX>
__device__ __forceinline__ void convt2_compute(
    const float* __restrict__ x2, const float* __restrict__ wb,
    int my, int py, int co, u64* A)
{
#pragma unroll 4
    for (int ci = 0; ci < 16; ci++) {
        const float* xc = x2 + ci * 256;            // 16x16 swizzled
#pragma unroll
        for (int d = 0; d < 2; d++) {
            int row = my + py + 1 - d;
            int sw = (row >> 1) & 3;
            const float* rp = xc + row * 16;
            float r[16];
#pragma unroll
            for (int tt = 0; tt < 4; tt++) {
                float4 vv = *(const float4*)(rp + ((tt ^ sw) << 2));
                r[4 * tt] = vv.x; r[4 * tt + 1] = vv.y;
                r[4 * tt + 2] = vv.z; r[4 * tt + 3] = vv.w;
            }
            int jy = 1 - py + 2 * d;
            u64 w0 = *(const u64*)&wb[((ci * 4 + jy) * 4 + (1 - PX)) * 8 + co];
            u64 w1 = *(const u64*)&wb[((ci * 4 + jy) * 4 + (3 - PX)) * 8 + co];
            u64 xa = pk(r[PX], r[PX]);
#pragma unroll
            for (int m = 0; m < 14; m++) {
                u64 xb = pk(r[PX + 1 + m], r[PX + 1 + m]);
                fma2(A[m], w1, xa);
                fma2(A[m], w0, xb);
                xa = xb;
            }
        }
    }
}

__global__ void __launch_bounds__(512, 2) conv_kernel(
    const float* __restrict__ cw1, const float* __restrict__ cb1,
    const float* __restrict__ cw2, const float* __restrict__ cb2,
    const float* __restrict__ cw3, const float* __restrict__ cb3,
    float* __restrict__ out)
{
    extern __shared__ float sm[];
    int tid = threadIdx.x;
    int half = tid >> 8, stid = tid & 255;
    int tile = blockIdx.x >> 3;          // 8 CTAs cover one 16-slot tile
    int g = d_tileg[tile];
    if (g < 0) return;
    int b = d_perm[blockIdx.x * 2 + half];   // may be -1 (padded slot)

    float* x2 = sm + half * SM_HALF;
    float* x3 = x2 + 4096;
    float* x1 = x3;                      // aliases x3 (dead before x3 written)
    float* wb = sm + SM_WB;

    int cls = stid >> 6;                 // warp-uniform parity class
    int py = cls >> 1, px = cls & 1;
    int v = stid & 63;

    // ---- halo-only zeroing of x1 and x2 (per half) ----
    for (int i = stid; i < 32 * 38; i += 256) {      // x1: 38 halo elems/ci
        int ci = i / 38, k = i - ci * 38;
        int row, col;
        if (k < 12)      { row = 0; col = k; }
        else if (k < 24) { row = 8; col = k - 12; }
        else { int k2 = k - 24; row = 1 + (k2 >> 1); col = (k2 & 1) * 8; }
        x1[ci * 108 + row * 12 + col] = 0.f;
    }
    for (int i = stid; i < 16 * 60; i += 256) {      // x2: 60 halo elems/ci
        int ci = i / 60, k = i - ci * 60;
        int row, col;
        if (k < 16)      { row = 0;  col = k; }
        else if (k < 32) { row = 15; col = k - 16; }
        else { int k2 = k - 32; row = 1 + (k2 >> 1); col = (k2 & 1) * 15; }
        x2[x2idx(ci, row, col)] = 0.f;
    }
    // load conv input [32,7,7] into padded x1 interior (stride 12), float4
    if (b >= 0) {
        const float4* src = (const float4*)(d_h2 + (size_t)b * 1568);
        for (int i4 = stid; i4 < 392; i4 += 256) {
            float4 w = src[i4];
            int base = i4 * 4;
#pragma unroll
            for (int e = 0; e < 4; e++) {
                int idx = base + e;
                int ci = idx / 49, rem = idx - ci * 49;
                int rr = rem / 7, cc = rem - rr * 7;
                float val = (e == 0) ? w.x : (e == 1) ? w.y : (e == 2) ? w.z : w.w;
                x1[ci * 108 + (rr + 1) * 12 + cc + 1] = val;
            }
        }
    }

    // ---- convT1: [32,7,7] -> [16,14,14], cw1 staged in 2 halves ----
    int my1 = v >> 3, co1 = (v & 7) * 2;             // valid when v < 56
    u64 A1c[7];
#pragma unroll
    for (int m = 0; m < 7; m++) A1c[m] = 0ULL;

    for (int hc = 0; hc < 2; hc++) {
        __syncthreads();
        for (int i4 = tid; i4 < 1024; i4 += 512) {   // 4096 floats, float4 LDG
            float4 w = ((const float4*)(cw1 + (size_t)g * 8192 + hc * 4096))[i4];
            int base = i4 * 4;
            int ci = base >> 8, cc = (base >> 4) & 15, jy = (base >> 2) & 3;
            float* dst = &wb[((ci * 4 + jy) * 4) * 16 + cc];
            dst[0] = w.x; dst[16] = w.y; dst[32] = w.z; dst[48] = w.w;
        }
        __syncthreads();
        if (v < 56) {
            const float* x1q = x1 + hc * 16 * 108;
            if (px == 0) convt1_half<0>(x1q, wb, my1, py, co1, A1c);
            else         convt1_half<1>(x1q, wb, my1, py, co1, A1c);
        }
    }
    if (v < 56) {
        float bb0 = cb1[g * 16 + co1], bb1 = cb1[g * 16 + co1 + 1];
        int oy = 2 * my1 + py;
#pragma unroll
        for (int m = 0; m < 7; m++) {
            int ox = 2 * m + px;
            float lo, hi; upk(A1c[m], lo, hi);
            x2[x2idx(co1,     oy + 1, ox + 1)] = lrelu(lo + bb0);
            x2[x2idx(co1 + 1, oy + 1, ox + 1)] = lrelu(hi + bb1);
        }
    }
    __syncthreads();     // convT1 done; x1 dead

    // halo-zero x3 (per half), stage cw2 + cw3 (all 512 threads)
    for (int i = stid; i < 8 * 116; i += 256) {
        int ci = i / 116, k = i - ci * 116;
        int row, col;
        if (k < 30)      { row = 0;  col = k; }
        else if (k < 60) { row = 29; col = k - 30; }
        else { int k2 = k - 60; row = 1 + (k2 >> 1); col = (k2 & 1) * 29; }
        x3[x3idx(ci, row, col)] = 0.f;
    }
    if (tid < 512) {                                  // 2048 floats, 1 f4/thread
        int i4 = tid;
        float4 w = ((const float4*)(cw2 + (size_t)g * 2048))[i4];
        int base = i4 * 4;
        int ci = base >> 7, cc = (base >> 4) & 7, jy = (base >> 2) & 3;
        float* dst = &wb[((ci * 4 + jy) * 4) * 8 + cc];
        dst[0] = w.x; dst[8] = w.y; dst[16] = w.z; dst[24] = w.w;
    }
    if (tid < 72) wb[2048 + tid] = cw3[g * 72 + tid];
    __syncthreads();

    // ---- convT2: [16,14,14] -> [8,28,28] ----
    if (v < 56) {
        int my = v >> 2, co = (v & 3) * 2;
        u64 A2c[14];
#pragma unroll
        for (int m = 0; m < 14; m++) A2c[m] = 0ULL;
        if (px == 0) convt2_compute<0>(x2, wb, my, py, co, A2c);
        else         convt2_compute<1>(x2, wb, my, py, co, A2c);
        float bb0 = cb2[g * 8 + co], bb1 = cb2[g * 8 + co + 1];
        int oy = 2 * my + py;
#pragma unroll
        for (int m = 0; m < 14; m++) {
            int ox = 2 * m + px;
            float lo, hi; upk(A2c[m], lo, hi);
            x3[x3idx(co,     oy + 1, ox + 1)] = lrelu(lo + bb0);
            x3[x3idx(co + 1, oy + 1, ox + 1)] = lrelu(hi + bb1);
        }
    }
    __syncthreads();

    // ---- convT3 (stride1 k3 p1): [8,28,28] -> [1,28,28], tanh ----
    if (stid < 196 && b >= 0) {
        int oy = stid / 7, s = stid - oy * 7;        // s in 0..6
        float bb = cb3[g];
        float acc[4];
#pragma unroll
        for (int u = 0; u < 4; u++) acc[u] = bb;
        const float* w3 = wb + 2048;
        for (int ci = 0; ci < 8; ci++) {
#pragma unroll
            for (int jy = 0; jy < 3; jy++) {
                int row = oy + 2 - jy;
                int sw = row & 7;
                const float* base = x3 + (ci * 30 + row) * 32;
                float r[8];
                float4 v0 = *(const float4*)(base + ((s ^ sw) << 2));
                float4 v1 = *(const float4*)(base + (((s + 1) ^ sw) << 2));
                r[0] = v0.x; r[1] = v0.y; r[2] = v0.z; r[3] = v0.w;
                r[4] = v1.x; r[5] = v1.y; r[6] = v1.z; r[7] = v1.w;
                const float* wr = w3 + ci * 9 + jy * 3;
#pragma unroll
                for (int jx = 0; jx < 3; jx++) {
                    float wv = wr[jx];
#pragma unroll
                    for (int u = 0; u < 4; u++)
                        acc[u] += wv * r[u + 2 - jx];
                }
            }
        }
        float4 o;
        o.x = tanhf(acc[0]); o.y = tanhf(acc[1]);
        o.z = tanhf(acc[2]); o.w = tanhf(acc[3]);
        *(float4*)(out + (size_t)b * 784 + oy * 28 + s * 4) = o;
    }
}

// ---------------- launch ----------------
extern "C" void kernel_launch(void* const* d_in, const int* in_sizes, int n_in,
                              void* d_out, int out_size)
{
    (void)in_sizes; (void)n_in; (void)out_size;
    const float* z   = (const float*)d_in[0];
    const int*   gi  = (const int*)d_in[1];
    const float* W1  = (const float*)d_in[2];
    const float* b1  = (const float*)d_in[3];
    const float* W2  = (const float*)d_in[4];
    const float* b2  = (const float*)d_in[5];
    const float* cw1 = (const float*)d_in[6];
    const float* cb1 = (const float*)d_in[7];
    const float* cw2 = (const float*)d_in[8];
    const float* cb2 = (const float*)d_in[9];
    const float* cw3 = (const float*)d_in[10];
    const float* cb3 = (const float*)d_in[11];
    float* out = (float*)d_out;

    group_kernel<<<1, 256>>>(gi);
    fc1_kernel<<<NTILES, 256>>>(z, W1, b1);
    fc2_kernel<<<dim3(NTILES, 4), 224>>>(W2, b2);
    cudaFuncSetAttribute(conv_kernel,
                         cudaFuncAttributeMaxDynamicSharedMemorySize,
                         SM_TOTALF * 4);
    conv_kernel<<<NTILES * 8, 512, SM_TOTALF * 4>>>(cw1, cb1, cw2, cb2,
                                                    cw3, cb3, out);
}